// round 5
// baseline (speedup 1.0000x reference)
#include <cuda_runtime.h>
#include <cuda_bf16.h>

// ---------------- problem constants ----------------
#define BATCH 2
#define SEQ   2048
#define EMB   1024
#define HEADS 16
#define DK    64
#define MTOK  (BATCH * SEQ)            // 4096
#define ZBH   (BATCH * HEADS)          // 32

// ---------------- device scratch (sanctioned workaround) ----------------
__device__ float g_q[(size_t)MTOK * EMB];                   // [B,S,E] (b,s,h,d)
__device__ float g_k[(size_t)MTOK * EMB];
__device__ float g_v[(size_t)MTOK * EMB];
__device__ float g_att[(size_t)MTOK * EMB];
__device__ float g_scores[(size_t)ZBH * SEQ * SEQ];         // 512 MB
__device__ unsigned char g_mask[BATCH * SEQ];               // canonical 0/1

// ---------------- mask canonicalization ----------------
// jax bool mask may be delivered as uint8 (1B), int32 (0/1) or float32 (0/1).
// Classify using only the first 4096 bytes (safe under every interpretation),
// then write canonical bytes to g_mask. Deterministic each launch.
__global__ void mask_canon_kernel(const void* __restrict__ raw) {
    __shared__ int sInt, sFloat;
    int t = threadIdx.x;
    if (t == 0) { sInt = 1; sFloat = 1; }
    __syncthreads();
    const unsigned int* w = (const unsigned int*)raw;
    int okInt = 1, okFloat = 1;
    for (int i = t; i < (BATCH * SEQ) / 4; i += 256) {   // first 4096 bytes
        unsigned int v = w[i];
        if (v > 1u) okInt = 0;
        if (v != 0u && v != 0x3F800000u) okFloat = 0;
    }
    if (!okInt)   atomicAnd(&sInt, 0);
    if (!okFloat) atomicAnd(&sFloat, 0);
    __syncthreads();
    if (sInt) {                       // int32 0/1
        const int* ip = (const int*)raw;
        for (int i = t; i < BATCH * SEQ; i += 256)
            g_mask[i] = (unsigned char)(ip[i] != 0);
    } else if (sFloat) {              // float32 0/1
        const float* fp = (const float*)raw;
        for (int i = t; i < BATCH * SEQ; i += 256)
            g_mask[i] = (unsigned char)(fp[i] != 0.0f);
    } else {                          // uint8 / int8 bool
        const unsigned char* cp = (const unsigned char*)raw;
        for (int i = t; i < BATCH * SEQ; i += 256)
            g_mask[i] = (unsigned char)(cp[i] != 0);
    }
}

// ---------------- generic batched tiled SGEMM ----------------
// C[z] = alpha * A[z] * op(B[z])
//   A: row-major  A[m*lda + k]
//   B: BKMAJOR ? B[n*ldb + k]  (NT, weights / K-matrix)
//             : B[k*ldb + n]  (NN, V-matrix)
// Per-z offsets: off = (z/zdiv)*Outer + (z%zdiv)*Inner (elements).
// All dims must divide tiles exactly (they do for every call site here).
template<int BM, int BN, int BK, int TM, int TN, bool BKMAJOR>
__global__ void __launch_bounds__(256)
sgemm_kernel(const float* __restrict__ A, int lda, long long aO, long long aI,
             const float* __restrict__ B, int ldb, long long bO, long long bI,
             float*       __restrict__ C, int ldc, long long cO, long long cI,
             int K, int zdiv, float alpha)
{
    __shared__ __align__(16) float As[BK][BM];
    __shared__ __align__(16) float Bs[BK][BN];

    const int z  = blockIdx.z;
    const int zo = z / zdiv, zi = z % zdiv;
    A += (size_t)((long long)zo * aO + (long long)zi * aI);
    B += (size_t)((long long)zo * bO + (long long)zi * bI);
    C += (size_t)((long long)zo * cO + (long long)zi * cI);

    const int m0 = blockIdx.y * BM;
    const int n0 = blockIdx.x * BN;
    const int t  = threadIdx.x;

    constexpr int BK4 = BK / 4;            // float4 chunks along k
    const int arow = t / BK4;              // 0..(256/BK4 - 1)
    const int akq  = t % BK4;
    constexpr int AROWS_PER = 256 / BK4;

    const int tx = t % (BN / TN);
    const int ty = t / (BN / TN);

    float acc[TM][TN];
    #pragma unroll
    for (int i = 0; i < TM; i++)
        #pragma unroll
        for (int j = 0; j < TN; j++) acc[i][j] = 0.0f;

    for (int k0 = 0; k0 < K; k0 += BK) {
        // ---- load A tile (BM x BK), store transposed As[k][m] ----
        #pragma unroll
        for (int r = arow; r < BM; r += AROWS_PER) {
            float4 v = *(const float4*)(A + (size_t)(m0 + r) * lda + k0 + akq * 4);
            As[akq * 4 + 0][r] = v.x;
            As[akq * 4 + 1][r] = v.y;
            As[akq * 4 + 2][r] = v.z;
            As[akq * 4 + 3][r] = v.w;
        }
        // ---- load B tile ----
        if constexpr (BKMAJOR) {
            #pragma unroll
            for (int r = arow; r < BN; r += AROWS_PER) {
                float4 v = *(const float4*)(B + (size_t)(n0 + r) * ldb + k0 + akq * 4);
                Bs[akq * 4 + 0][r] = v.x;
                Bs[akq * 4 + 1][r] = v.y;
                Bs[akq * 4 + 2][r] = v.z;
                Bs[akq * 4 + 3][r] = v.w;
            }
        } else {
            constexpr int BN4 = BN / 4;
            for (int idx = t; idx < BK * BN4; idx += 256) {
                int kk = idx / BN4, nn = idx % BN4;
                *(float4*)&Bs[kk][nn * 4] =
                    *(const float4*)(B + (size_t)(k0 + kk) * ldb + n0 + nn * 4);
            }
        }
        __syncthreads();

        // ---- compute ----
        #pragma unroll
        for (int kk = 0; kk < BK; kk++) {
            float a[TM], bb[TN];
            #pragma unroll
            for (int i = 0; i < TM; i += 4)
                *(float4*)&a[i] = *(float4*)&As[kk][ty * TM + i];
            #pragma unroll
            for (int j = 0; j < TN; j += 4)
                *(float4*)&bb[j] = *(float4*)&Bs[kk][tx * TN + j];
            #pragma unroll
            for (int i = 0; i < TM; i++)
                #pragma unroll
                for (int j = 0; j < TN; j++)
                    acc[i][j] += a[i] * bb[j];
        }
        __syncthreads();
    }

    // ---- epilogue ----
    #pragma unroll
    for (int i = 0; i < TM; i++) {
        float* crow = C + (size_t)(m0 + ty * TM + i) * ldc + n0 + tx * TN;
        #pragma unroll
        for (int j = 0; j < TN; j += 4) {
            float4 v;
            v.x = alpha * acc[i][j + 0];
            v.y = alpha * acc[i][j + 1];
            v.z = alpha * acc[i][j + 2];
            v.w = alpha * acc[i][j + 3];
            *(float4*)(crow + j) = v;
        }
    }
}

// ---------------- masked row softmax (in place) ----------------
// One block per row; row = (b*H + h)*S + i; 2048 cols; values stay in regs.
__global__ void __launch_bounds__(256) softmax_kernel(float* __restrict__ sc)
{
    const int row = blockIdx.x;             // 0 .. ZBH*SEQ-1
    const int z   = row >> 11;              // / SEQ
    const int b   = z >> 4;                 // / HEADS
    float* p = sc + ((size_t)row << 11);
    const unsigned char* mrow = g_mask + (b << 11);
    const int t = threadIdx.x;

    __shared__ float sred[8];
    __shared__ float sbc;

    float vals[8];
    float mx = -3.402823e38f;
    #pragma unroll
    for (int u = 0; u < 8; u++) {
        int j = u * 256 + t;
        float v = mrow[j] ? -1e9f : p[j];
        vals[u] = v;
        mx = fmaxf(mx, v);
    }
    #pragma unroll
    for (int o = 16; o > 0; o >>= 1)
        mx = fmaxf(mx, __shfl_xor_sync(0xffffffffu, mx, o));
    if ((t & 31) == 0) sred[t >> 5] = mx;
    __syncthreads();
    if (t == 0) {
        float m = sred[0];
        #pragma unroll
        for (int i = 1; i < 8; i++) m = fmaxf(m, sred[i]);
        sbc = m;
    }
    __syncthreads();
    mx = sbc;

    float sum = 0.0f;
    #pragma unroll
    for (int u = 0; u < 8; u++) {
        float e = __expf(vals[u] - mx);
        vals[u] = e;
        sum += e;
    }
    #pragma unroll
    for (int o = 16; o > 0; o >>= 1)
        sum += __shfl_xor_sync(0xffffffffu, sum, o);
    __syncthreads();                 // protect sred reuse
    if ((t & 31) == 0) sred[t >> 5] = sum;
    __syncthreads();
    if (t == 0) {
        float s = 0.0f;
        #pragma unroll
        for (int i = 0; i < 8; i++) s += sred[i];
        sbc = 1.0f / s;
    }
    __syncthreads();
    const float inv = sbc;
    #pragma unroll
    for (int u = 0; u < 8; u++)
        p[u * 256 + t] = vals[u] * inv;
}

// ---------------- launch ----------------
extern "C" void kernel_launch(void* const* d_in, const int* in_sizes, int n_in,
                              void* d_out, int out_size)
{
    const float* x  = (const float*)d_in[0];
    const void*  mk = d_in[1];
    const float* wq = (const float*)d_in[2];
    const float* wk = (const float*)d_in[3];
    const float* wv = (const float*)d_in[4];
    const float* wo = (const float*)d_in[5];
    float* out = (float*)d_out;

    float *pq, *pk, *pv, *patt, *psc;
    cudaGetSymbolAddress((void**)&pq,   g_q);
    cudaGetSymbolAddress((void**)&pk,   g_k);
    cudaGetSymbolAddress((void**)&pv,   g_v);
    cudaGetSymbolAddress((void**)&patt, g_att);
    cudaGetSymbolAddress((void**)&psc,  g_scores);

    const dim3 blk(256);

    // 0) canonicalize mask
    mask_canon_kernel<<<1, 256>>>(mk);

    // 1) Q/K/V projections: [4096,1024] = x @ W^T  (NT)
    const dim3 gproj(EMB / 128, MTOK / 128, 1);
    sgemm_kernel<128,128,8,8,8,true><<<gproj, blk>>>(
        x, EMB, 0, 0,  wq, EMB, 0, 0,  pq, EMB, 0, 0,  EMB, 1, 1.0f);
    sgemm_kernel<128,128,8,8,8,true><<<gproj, blk>>>(
        x, EMB, 0, 0,  wk, EMB, 0, 0,  pk, EMB, 0, 0,  EMB, 1, 1.0f);
    sgemm_kernel<128,128,8,8,8,true><<<gproj, blk>>>(
        x, EMB, 0, 0,  wv, EMB, 0, 0,  pv, EMB, 0, 0,  EMB, 1, 1.0f);

    // 2) scores[z] = Q[z] K[z]^T / sqrt(Dk)   z = b*H+h, NT, K=64
    //    A/B offset: b*S*E + h*DK ; C offset: z*S*S
    const long long SE  = (long long)SEQ * EMB;        // 2097152
    const long long SS  = (long long)SEQ * SEQ;        // 4194304
    const dim3 gsc(SEQ / 128, SEQ / 128, ZBH);
    sgemm_kernel<128,128,8,8,8,true><<<gsc, blk>>>(
        pq, EMB, SE, DK,
        pk, EMB, SE, DK,
        psc, SEQ, (long long)HEADS * SS, SS,
        DK, HEADS, 0.125f);

    // 3) masked softmax over keys, in place
    softmax_kernel<<<ZBH * SEQ, 256>>>(psc);

    // 4) att[z] = P[z] @ V[z]   NN, M=2048, N=64, K=2048
    const dim3 gpv(DK / 64, SEQ / 128, ZBH);
    sgemm_kernel<128,64,8,8,4,false><<<gpv, blk>>>(
        psc, SEQ, (long long)HEADS * SS, SS,
        pv,  EMB, SE, DK,
        patt, EMB, SE, DK,
        SEQ, HEADS, 1.0f);

    // 5) out = att @ wo^T  (NT)
    sgemm_kernel<128,128,8,8,8,true><<<gproj, blk>>>(
        patt, EMB, 0, 0,  wo, EMB, 0, 0,  out, EMB, 0, 0,  EMB, 1, 1.0f);
}

// round 7
// speedup vs baseline: 2.1201x; 2.1201x over previous
#include <cuda_runtime.h>
#include <cuda_bf16.h>
#include <cstdint>

// ---------------- problem constants ----------------
#define BATCH 2
#define SEQ   2048
#define EMB   1024
#define HEADS 16
#define DK    64
#define MTOK  (BATCH * SEQ)            // 4096
#define ZBH   (BATCH * HEADS)          // 32

// ---------------- device scratch ----------------
__device__ __align__(16) float         g_scores[(size_t)ZBH * SEQ * SEQ];   // 512 MB
__device__ __align__(16) __nv_bfloat16 g_p_hi [(size_t)ZBH * SEQ * SEQ];    // 256 MB
__device__ __align__(16) __nv_bfloat16 g_p_lo [(size_t)ZBH * SEQ * SEQ];    // 256 MB
__device__ __align__(16) __nv_bfloat16 g_x_hi [(size_t)MTOK * EMB];
__device__ __align__(16) __nv_bfloat16 g_x_lo [(size_t)MTOK * EMB];
__device__ __align__(16) __nv_bfloat16 g_w_hi [4][(size_t)EMB * EMB];
__device__ __align__(16) __nv_bfloat16 g_w_lo [4][(size_t)EMB * EMB];
__device__ __align__(16) __nv_bfloat16 g_q_hi [(size_t)MTOK * EMB];
__device__ __align__(16) __nv_bfloat16 g_q_lo [(size_t)MTOK * EMB];
__device__ __align__(16) __nv_bfloat16 g_k_hi [(size_t)MTOK * EMB];
__device__ __align__(16) __nv_bfloat16 g_k_lo [(size_t)MTOK * EMB];
__device__ __align__(16) __nv_bfloat16 g_vt_hi[(size_t)BATCH * EMB * SEQ];  // [b][e][s]
__device__ __align__(16) __nv_bfloat16 g_vt_lo[(size_t)BATCH * EMB * SEQ];
__device__ __align__(16) __nv_bfloat16 g_at_hi[(size_t)MTOK * EMB];
__device__ __align__(16) __nv_bfloat16 g_at_lo[(size_t)MTOK * EMB];
__device__ __align__(16) unsigned char g_mask[BATCH * SEQ];

// ---------------- base-ISA PTX helpers (no 'a'-suffix features!) ----------------
__device__ __forceinline__ uint32_t s2u(const void* p) {
    uint32_t a;
    asm("{ .reg .u64 t; cvta.to.shared.u64 t, %1; cvt.u32.u64 %0, t; }" : "=r"(a) : "l"(p));
    return a;
}
__device__ __forceinline__ void cpa16(uint32_t s, const void* g) {
    asm volatile("cp.async.cg.shared.global [%0], [%1], 16;" :: "r"(s), "l"(g));
}
#define CP_COMMIT() asm volatile("cp.async.commit_group;" ::: "memory")
#define CP_WAIT1()  asm volatile("cp.async.wait_group 1;"  ::: "memory")
#define CP_WAIT0()  asm volatile("cp.async.wait_group 0;"  ::: "memory")

__device__ __forceinline__ void ldsm4(uint32_t a, uint32_t r[4]) {
    asm volatile("ldmatrix.sync.aligned.m8n8.x4.shared.b16 {%0,%1,%2,%3}, [%4];"
        : "=r"(r[0]), "=r"(r[1]), "=r"(r[2]), "=r"(r[3]) : "r"(a));
}
__device__ __forceinline__ void ldsm2(uint32_t a, uint32_t r[2]) {
    asm volatile("ldmatrix.sync.aligned.m8n8.x2.shared.b16 {%0,%1}, [%2];"
        : "=r"(r[0]), "=r"(r[1]) : "r"(a));
}
__device__ __forceinline__ void mma16816(float c[4], const uint32_t a[4], const uint32_t b[2]) {
    asm volatile(
        "mma.sync.aligned.m16n8k16.row.col.f32.bf16.bf16.f32 "
        "{%0,%1,%2,%3}, {%4,%5,%6,%7}, {%8,%9}, {%0,%1,%2,%3};"
        : "+f"(c[0]), "+f"(c[1]), "+f"(c[2]), "+f"(c[3])
        : "r"(a[0]), "r"(a[1]), "r"(a[2]), "r"(a[3]), "r"(b[0]), "r"(b[1]));
}

// ---------------- mask canonicalization ----------------
__global__ void mask_canon_kernel(const void* __restrict__ raw) {
    __shared__ int sInt, sFloat;
    int t = threadIdx.x;
    if (t == 0) { sInt = 1; sFloat = 1; }
    __syncthreads();
    const unsigned int* w = (const unsigned int*)raw;
    int okInt = 1, okFloat = 1;
    for (int i = t; i < (BATCH * SEQ) / 4; i += 256) {
        unsigned int v = w[i];
        if (v > 1u) okInt = 0;
        if (v != 0u && v != 0x3F800000u) okFloat = 0;
    }
    if (!okInt)   atomicAnd(&sInt, 0);
    if (!okFloat) atomicAnd(&sFloat, 0);
    __syncthreads();
    if (sInt) {
        const int* ip = (const int*)raw;
        for (int i = t; i < BATCH * SEQ; i += 256) g_mask[i] = (unsigned char)(ip[i] != 0);
    } else if (sFloat) {
        const float* fp = (const float*)raw;
        for (int i = t; i < BATCH * SEQ; i += 256) g_mask[i] = (unsigned char)(fp[i] != 0.0f);
    } else {
        const unsigned char* cp = (const unsigned char*)raw;
        for (int i = t; i < BATCH * SEQ; i += 256) g_mask[i] = (unsigned char)(cp[i] != 0);
    }
}

// ---------------- fp32 -> bf16 hi/lo split ----------------
__global__ void __launch_bounds__(256) split_kernel(
    const float* __restrict__ in, __nv_bfloat16* __restrict__ h,
    __nv_bfloat16* __restrict__ l, int n4)
{
    int i = blockIdx.x * 256 + threadIdx.x;
    if (i >= n4) return;
    float4 v = ((const float4*)in)[i];
    float a[4] = { v.x, v.y, v.z, v.w };
    __nv_bfloat16 hv[4], lv[4];
    #pragma unroll
    for (int q = 0; q < 4; q++) {
        hv[q] = __float2bfloat16(a[q]);
        lv[q] = __float2bfloat16(a[q] - __bfloat162float(hv[q]));
    }
    ((uint2*)h)[i] = *(uint2*)hv;
    ((uint2*)l)[i] = *(uint2*)lv;
}

// ---------------- HMMA split-bf16 GEMM ----------------
// D[m][n] = alpha * sum_k A[m][k] * B[n][k]   (both K-major, NT). 3-split:
// D = Ah*Bh + Ah*Bl + Al*Bh, fp32 accumulators.
// 128 x BN CTA tile, 8 warps (2 x 4), BK=32, cp.async double buffer.
// Smem rows padded to 80B -> (5r+c)%8 covers all bank-groups (conflict-free ldmatrix).
// EPI: 0 = fp32 C0 ; 1 = bf16 hi/lo planes C0/C1 ; 2 = V-transpose hi/lo planes.
template<int BN, int EPI>
__global__ void __launch_bounds__(256, 1)
mm_hmma(const __nv_bfloat16* __restrict__ Ah, const __nv_bfloat16* __restrict__ Al,
        int lda, long long aO, long long aI,
        const __nv_bfloat16* __restrict__ Bh, const __nv_bfloat16* __restrict__ Bl,
        int ldb, long long bO, long long bI,
        void* __restrict__ C0, void* __restrict__ C1,
        int ldc, long long cO, long long cI,
        int K, int zdiv, float alpha)
{
    constexpr int BM  = 128;
    constexpr int MF  = 4;                 // m16 fragments per warp (warp m-tile 64)
    constexpr int NF  = BN / 32;           // n8 fragments per warp (warp n-tile BN/4)
    constexpr int APL = BM * 80;           // bytes per A plane per stage
    constexpr int BPL = BN * 80;
    constexpr int STG = 2 * APL + 2 * BPL;

    extern __shared__ __align__(16) char smem[];
    const uint32_t sb = s2u(smem);
    const int t = threadIdx.x, wid = t >> 5, lid = t & 31;
    const int wm = wid >> 2, wn = wid & 3;
    const int warp_m0 = wm * 64;
    const int warp_n0 = wn * (NF * 8);

    const int z  = blockIdx.z;
    const int zo = z / zdiv, zi = z - zo * zdiv;
    const size_t aoff = (size_t)((long long)zo * aO + (long long)zi * aI);
    const size_t boff = (size_t)((long long)zo * bO + (long long)zi * bI);
    Ah += aoff; Al += aoff; Bh += boff; Bl += boff;
    const int m0 = blockIdx.y * BM, n0 = blockIdx.x * BN;

    float acc[MF][NF][4];
    #pragma unroll
    for (int i = 0; i < MF; i++)
        #pragma unroll
        for (int j = 0; j < NF; j++)
            #pragma unroll
            for (int q = 0; q < 4; q++) acc[i][j][q] = 0.0f;

    auto load_tile = [&](int st, int c) {
        const int k0 = c << 5;
        const uint32_t sA = sb + st * STG;
        const uint32_t sB = sA + 2 * APL;
        #pragma unroll
        for (int i = t; i < BM * 4; i += 256) {
            const int row = i >> 2, cc = i & 3;
            const size_t go = (size_t)(m0 + row) * lda + k0 + cc * 8;
            const uint32_t so = sA + row * 80 + cc * 16;
            cpa16(so, Ah + go);
            cpa16(so + APL, Al + go);
        }
        #pragma unroll
        for (int i = t; i < BN * 4; i += 256) {
            const int row = i >> 2, cc = i & 3;
            const size_t go = (size_t)(n0 + row) * ldb + k0 + cc * 8;
            const uint32_t so = sB + row * 80 + cc * 16;
            cpa16(so, Bh + go);
            cpa16(so + BPL, Bl + go);
        }
    };

    const int nt = K >> 5;
    load_tile(0, 0);
    CP_COMMIT();

    for (int c = 0; c < nt; ++c) {
        if (c + 1 < nt) {
            load_tile((c + 1) & 1, c + 1);
            CP_COMMIT();
            CP_WAIT1();
        } else {
            CP_WAIT0();
        }
        __syncthreads();

        const uint32_t sA = sb + (c & 1) * STG;
        const uint32_t sB = sA + 2 * APL;
        #pragma unroll
        for (int ks = 0; ks < 2; ++ks) {
            uint32_t ah[MF][4], al[MF][4];
            #pragma unroll
            for (int mf = 0; mf < MF; ++mf) {
                const int lrow = warp_m0 + mf * 16 + (lid & 15);
                const int lch  = ks * 2 + (lid >> 4);
                const uint32_t ad = sA + lrow * 80 + lch * 16;
                ldsm4(ad, ah[mf]);
                ldsm4(ad + APL, al[mf]);
            }
            uint32_t bh[NF][2], bl[NF][2];
            #pragma unroll
            for (int nf = 0; nf < NF; ++nf) {
                const int lrow = warp_n0 + nf * 8 + (lid & 7);
                const int lch  = ks * 2 + ((lid >> 3) & 1);
                const uint32_t bd = sB + lrow * 80 + lch * 16;
                ldsm2(bd, bh[nf]);
                ldsm2(bd + BPL, bl[nf]);
            }
            #pragma unroll
            for (int mf = 0; mf < MF; ++mf)
                #pragma unroll
                for (int nf = 0; nf < NF; ++nf) {
                    mma16816(acc[mf][nf], ah[mf], bh[nf]);
                    mma16816(acc[mf][nf], ah[mf], bl[nf]);
                    mma16816(acc[mf][nf], al[mf], bh[nf]);
                }
        }
        __syncthreads();
    }

    // ---- epilogue ----
    const int qrow = lid >> 2, qcol = (lid & 3) * 2;
    #pragma unroll
    for (int mf = 0; mf < MF; ++mf) {
        #pragma unroll
        for (int h = 0; h < 2; ++h) {
            const int m = m0 + warp_m0 + mf * 16 + qrow + h * 8;
            if constexpr (EPI == 0) {
                float* C = (float*)C0 + (size_t)((long long)zo * cO + (long long)zi * cI)
                         + (size_t)m * ldc + n0 + warp_n0 + qcol;
                #pragma unroll
                for (int nf = 0; nf < NF; ++nf) {
                    float2 v;
                    v.x = alpha * acc[mf][nf][h * 2 + 0];
                    v.y = alpha * acc[mf][nf][h * 2 + 1];
                    *(float2*)(C + nf * 8) = v;
                }
            } else if constexpr (EPI == 1) {
                const size_t base = (size_t)((long long)zo * cO + (long long)zi * cI)
                                  + (size_t)m * ldc + n0 + warp_n0 + qcol;
                __nv_bfloat16* H = (__nv_bfloat16*)C0 + base;
                __nv_bfloat16* L = (__nv_bfloat16*)C1 + base;
                #pragma unroll
                for (int nf = 0; nf < NF; ++nf) {
                    float v0 = alpha * acc[mf][nf][h * 2 + 0];
                    float v1 = alpha * acc[mf][nf][h * 2 + 1];
                    __nv_bfloat16 h0 = __float2bfloat16(v0);
                    __nv_bfloat16 h1 = __float2bfloat16(v1);
                    __nv_bfloat16 l0 = __float2bfloat16(v0 - __bfloat162float(h0));
                    __nv_bfloat16 l1 = __float2bfloat16(v1 - __bfloat162float(h1));
                    __nv_bfloat162 hp; hp.x = h0; hp.y = h1;
                    __nv_bfloat162 lp; lp.x = l0; lp.y = l1;
                    *(__nv_bfloat162*)(H + nf * 8) = hp;
                    *(__nv_bfloat162*)(L + nf * 8) = lp;
                }
            } else {  // EPI == 2 : V transpose -> out[b][e][s]
                const int bb = m >> 11, sq = m & (SEQ - 1);
                __nv_bfloat16* H = (__nv_bfloat16*)C0;
                __nv_bfloat16* L = (__nv_bfloat16*)C1;
                #pragma unroll
                for (int nf = 0; nf < NF; ++nf) {
                    #pragma unroll
                    for (int q = 0; q < 2; ++q) {
                        const float v = acc[mf][nf][h * 2 + q];
                        const __nv_bfloat16 hv = __float2bfloat16(v);
                        const __nv_bfloat16 lv = __float2bfloat16(v - __bfloat162float(hv));
                        const int e = n0 + warp_n0 + nf * 8 + qcol + q;
                        const size_t ad = (size_t)bb * ((size_t)EMB * SEQ)
                                        + (size_t)e * SEQ + sq;
                        H[ad] = hv; L[ad] = lv;
                    }
                }
            }
        }
    }
}

// ---------------- masked row softmax: fp32 scores -> bf16 hi/lo P ----------------
__global__ void __launch_bounds__(256) softmax_kernel(
    const float* __restrict__ sc,
    __nv_bfloat16* __restrict__ ph_, __nv_bfloat16* __restrict__ pl_)
{
    const int row = blockIdx.x;            // (b*H+h)*S + q
    const int z   = row >> 11;
    const int b   = z >> 4;
    const float* p = sc + ((size_t)row << 11);
    const unsigned char* mrow = g_mask + (b << 11);
    const int t = threadIdx.x;

    __shared__ float sred[8];
    __shared__ float sbc;

    float vals[8];
    {
        const float4 va = ((const float4*)p)[t * 2];
        const float4 vb = ((const float4*)p)[t * 2 + 1];
        vals[0] = va.x; vals[1] = va.y; vals[2] = va.z; vals[3] = va.w;
        vals[4] = vb.x; vals[5] = vb.y; vals[6] = vb.z; vals[7] = vb.w;
    }
    unsigned char m8[8];
    *(uint2*)m8 = ((const uint2*)mrow)[t];

    float mx = -3.402823e38f;
    #pragma unroll
    for (int u = 0; u < 8; u++) {
        if (m8[u]) vals[u] = -1e9f;
        mx = fmaxf(mx, vals[u]);
    }
    #pragma unroll
    for (int o = 16; o > 0; o >>= 1)
        mx = fmaxf(mx, __shfl_xor_sync(0xffffffffu, mx, o));
    if ((t & 31) == 0) sred[t >> 5] = mx;
    __syncthreads();
    if (t == 0) {
        float m = sred[0];
        #pragma unroll
        for (int i = 1; i < 8; i++) m = fmaxf(m, sred[i]);
        sbc = m;
    }
    __syncthreads();
    mx = sbc;

    float sum = 0.0f;
    #pragma unroll
    for (int u = 0; u < 8; u++) {
        float e = __expf(vals[u] - mx);
        vals[u] = e;
        sum += e;
    }
    #pragma unroll
    for (int o = 16; o > 0; o >>= 1)
        sum += __shfl_xor_sync(0xffffffffu, sum, o);
    __syncthreads();
    if ((t & 31) == 0) sred[t >> 5] = sum;
    __syncthreads();
    if (t == 0) {
        float s = 0.0f;
        #pragma unroll
        for (int i = 0; i < 8; i++) s += sred[i];
        sbc = 1.0f / s;
    }
    __syncthreads();
    const float inv = sbc;

    __nv_bfloat16 hv[8], lv[8];
    #pragma unroll
    for (int u = 0; u < 8; u++) {
        float v = vals[u] * inv;
        hv[u] = __float2bfloat16(v);
        lv[u] = __float2bfloat16(v - __bfloat162float(hv[u]));
    }
    const size_t o = ((size_t)row << 11) + (size_t)t * 8;
    *(uint4*)(ph_ + o) = *(uint4*)hv;
    *(uint4*)(pl_ + o) = *(uint4*)lv;
}

// ---------------- launch ----------------
extern "C" void kernel_launch(void* const* d_in, const int* in_sizes, int n_in,
                              void* d_out, int out_size)
{
    const float* x  = (const float*)d_in[0];
    const void*  mk = d_in[1];
    const float* wq = (const float*)d_in[2];
    const float* wk = (const float*)d_in[3];
    const float* wv = (const float*)d_in[4];
    const float* wo = (const float*)d_in[5];
    float* out = (float*)d_out;

    float* psc;
    __nv_bfloat16 *ph_, *pl_, *xh, *xl, *wh, *wl, *qh, *ql, *kh, *kl, *vth, *vtl, *ath, *atl;
    cudaGetSymbolAddress((void**)&psc, g_scores);
    cudaGetSymbolAddress((void**)&ph_, g_p_hi);
    cudaGetSymbolAddress((void**)&pl_, g_p_lo);
    cudaGetSymbolAddress((void**)&xh,  g_x_hi);
    cudaGetSymbolAddress((void**)&xl,  g_x_lo);
    cudaGetSymbolAddress((void**)&wh,  g_w_hi);
    cudaGetSymbolAddress((void**)&wl,  g_w_lo);
    cudaGetSymbolAddress((void**)&qh,  g_q_hi);
    cudaGetSymbolAddress((void**)&ql,  g_q_lo);
    cudaGetSymbolAddress((void**)&kh,  g_k_hi);
    cudaGetSymbolAddress((void**)&kl,  g_k_lo);
    cudaGetSymbolAddress((void**)&vth, g_vt_hi);
    cudaGetSymbolAddress((void**)&vtl, g_vt_lo);
    cudaGetSymbolAddress((void**)&ath, g_at_hi);
    cudaGetSymbolAddress((void**)&atl, g_at_lo);

    // dynamic smem: 2 stages * (2*A + 2*B) planes * 80B rows
    const int SM128 = 2 * (2 * 128 * 80 + 2 * 128 * 80);   // 81920
    const int SM64  = 2 * (2 * 128 * 80 + 2 * 64 * 80);    // 61440
    cudaFuncSetAttribute(mm_hmma<128, 0>, cudaFuncAttributeMaxDynamicSharedMemorySize, SM128);
    cudaFuncSetAttribute(mm_hmma<128, 1>, cudaFuncAttributeMaxDynamicSharedMemorySize, SM128);
    cudaFuncSetAttribute(mm_hmma<128, 2>, cudaFuncAttributeMaxDynamicSharedMemorySize, SM128);
    cudaFuncSetAttribute(mm_hmma<64, 1>,  cudaFuncAttributeMaxDynamicSharedMemorySize, SM64);

    // 0) canonicalize mask
    mask_canon_kernel<<<1, 256>>>(mk);

    // 1) fp32 -> bf16 hi/lo for x and weights
    const int NX4 = (MTOK * EMB) / 4, NW4 = (EMB * EMB) / 4;
    const size_t WSZ = (size_t)EMB * EMB;
    split_kernel<<<(NX4 + 255) / 256, 256>>>(x,  xh, xl, NX4);
    split_kernel<<<(NW4 + 255) / 256, 256>>>(wq, wh + 0 * WSZ, wl + 0 * WSZ, NW4);
    split_kernel<<<(NW4 + 255) / 256, 256>>>(wk, wh + 1 * WSZ, wl + 1 * WSZ, NW4);
    split_kernel<<<(NW4 + 255) / 256, 256>>>(wv, wh + 2 * WSZ, wl + 2 * WSZ, NW4);
    split_kernel<<<(NW4 + 255) / 256, 256>>>(wo, wh + 3 * WSZ, wl + 3 * WSZ, NW4);

    const long long SE = (long long)SEQ * EMB;
    const long long SS = (long long)SEQ * SEQ;
    const dim3 gproj(EMB / 128, MTOK / 128, 1);

    // 2) Q/K projections -> split planes ; V projection -> transposed split planes
    mm_hmma<128, 1><<<gproj, 256, SM128>>>(
        xh, xl, EMB, 0, 0,  wh + 0 * WSZ, wl + 0 * WSZ, EMB, 0, 0,
        qh, ql, EMB, 0, 0,  EMB, 1, 1.0f);
    mm_hmma<128, 1><<<gproj, 256, SM128>>>(
        xh, xl, EMB, 0, 0,  wh + 1 * WSZ, wl + 1 * WSZ, EMB, 0, 0,
        kh, kl, EMB, 0, 0,  EMB, 1, 1.0f);
    mm_hmma<128, 2><<<gproj, 256, SM128>>>(
        xh, xl, EMB, 0, 0,  wh + 2 * WSZ, wl + 2 * WSZ, EMB, 0, 0,
        vth, vtl, EMB, 0, 0,  EMB, 1, 1.0f);

    // 3) scores[z] = (Q K^T) / 8   (K = DK = 64)
    const dim3 gsc(SEQ / 128, SEQ / 128, ZBH);
    mm_hmma<128, 0><<<gsc, 256, SM128>>>(
        qh, ql, EMB, SE, DK,
        kh, kl, EMB, SE, DK,
        psc, nullptr, SEQ, (long long)HEADS * SS, SS,
        DK, HEADS, 0.125f);

    // 4) masked softmax -> P split planes
    softmax_kernel<<<ZBH * SEQ, 256>>>(psc, ph_, pl_);

    // 5) att[z] = P V   (B = V^T, NT) -> att split planes
    const dim3 gpv(1, SEQ / 128, ZBH);
    mm_hmma<64, 1><<<gpv, 256, SM64>>>(
        ph_, pl_, SEQ, (long long)HEADS * SS, SS,
        vth, vtl, SEQ, (long long)EMB * SEQ, (long long)DK * SEQ,
        ath, atl, EMB, SE, DK,
        SEQ, HEADS, 1.0f);

    // 6) out = att @ wo^T  (fp32 epilogue to d_out)
    mm_hmma<128, 0><<<gproj, 256, SM128>>>(
        ath, atl, EMB, 0, 0,  wh + 3 * WSZ, wl + 3 * WSZ, EMB, 0, 0,
        out, nullptr, EMB, 0, 0,  EMB, 1, 1.0f);
}

// round 8
// speedup vs baseline: 2.9152x; 1.3750x over previous
#include <cuda_runtime.h>
#include <cuda_bf16.h>
#include <cstdint>

// ---------------- problem constants ----------------
#define BATCH 2
#define SEQ   2048
#define EMB   1024
#define HEADS 16
#define DK    64
#define MTOK  (BATCH * SEQ)            // 4096
#define ZBH   (BATCH * HEADS)          // 32

// ---------------- device scratch ----------------
__device__ __align__(16) __nv_bfloat16 g_x_hi [(size_t)MTOK * EMB];
__device__ __align__(16) __nv_bfloat16 g_x_lo [(size_t)MTOK * EMB];
__device__ __align__(16) __nv_bfloat16 g_w_hi [4][(size_t)EMB * EMB];
__device__ __align__(16) __nv_bfloat16 g_w_lo [4][(size_t)EMB * EMB];
__device__ __align__(16) __nv_bfloat16 g_q_hi [(size_t)MTOK * EMB];
__device__ __align__(16) __nv_bfloat16 g_q_lo [(size_t)MTOK * EMB];
__device__ __align__(16) __nv_bfloat16 g_k_hi [(size_t)MTOK * EMB];
__device__ __align__(16) __nv_bfloat16 g_k_lo [(size_t)MTOK * EMB];
__device__ __align__(16) __nv_bfloat16 g_vt_hi[(size_t)BATCH * EMB * SEQ];  // [b][e][s]
__device__ __align__(16) __nv_bfloat16 g_vt_lo[(size_t)BATCH * EMB * SEQ];
__device__ __align__(16) __nv_bfloat16 g_at_hi[(size_t)MTOK * EMB];
__device__ __align__(16) __nv_bfloat16 g_at_lo[(size_t)MTOK * EMB];
__device__ __align__(16) unsigned char g_mask[BATCH * SEQ];

// ---------------- base-ISA PTX helpers ----------------
__device__ __forceinline__ uint32_t s2u(const void* p) {
    uint32_t a;
    asm("{ .reg .u64 t; cvta.to.shared.u64 t, %1; cvt.u32.u64 %0, t; }" : "=r"(a) : "l"(p));
    return a;
}
__device__ __forceinline__ void cpa16(uint32_t s, const void* g) {
    asm volatile("cp.async.cg.shared.global [%0], [%1], 16;" :: "r"(s), "l"(g));
}
#define CP_COMMIT() asm volatile("cp.async.commit_group;" ::: "memory")
#define CP_WAIT1()  asm volatile("cp.async.wait_group 1;"  ::: "memory")
#define CP_WAIT0()  asm volatile("cp.async.wait_group 0;"  ::: "memory")

__device__ __forceinline__ void ldsm4(uint32_t a, uint32_t r[4]) {
    asm volatile("ldmatrix.sync.aligned.m8n8.x4.shared.b16 {%0,%1,%2,%3}, [%4];"
        : "=r"(r[0]), "=r"(r[1]), "=r"(r[2]), "=r"(r[3]) : "r"(a));
}
__device__ __forceinline__ void ldsm2(uint32_t a, uint32_t r[2]) {
    asm volatile("ldmatrix.sync.aligned.m8n8.x2.shared.b16 {%0,%1}, [%2];"
        : "=r"(r[0]), "=r"(r[1]) : "r"(a));
}
__device__ __forceinline__ void mma16816(float c[4], const uint32_t a[4], const uint32_t b[2]) {
    asm volatile(
        "mma.sync.aligned.m16n8k16.row.col.f32.bf16.bf16.f32 "
        "{%0,%1,%2,%3}, {%4,%5,%6,%7}, {%8,%9}, {%0,%1,%2,%3};"
        : "+f"(c[0]), "+f"(c[1]), "+f"(c[2]), "+f"(c[3])
        : "r"(a[0]), "r"(a[1]), "r"(a[2]), "r"(a[3]), "r"(b[0]), "r"(b[1]));
}
// split two floats into packed bf16x2 hi and lo planes
__device__ __forceinline__ void split2(float a, float b, uint32_t& hi, uint32_t& lo) {
    __nv_bfloat16 ha = __float2bfloat16(a), hb = __float2bfloat16(b);
    __nv_bfloat16 la = __float2bfloat16(a - __bfloat162float(ha));
    __nv_bfloat16 lb = __float2bfloat16(b - __bfloat162float(hb));
    __nv_bfloat162 hv; hv.x = ha; hv.y = hb;
    __nv_bfloat162 lv; lv.x = la; lv.y = lb;
    hi = *(uint32_t*)&hv; lo = *(uint32_t*)&lv;
}

// ---------------- mask canonicalization ----------------
__global__ void mask_canon_kernel(const void* __restrict__ raw) {
    __shared__ int sInt, sFloat;
    int t = threadIdx.x;
    if (t == 0) { sInt = 1; sFloat = 1; }
    __syncthreads();
    const unsigned int* w = (const unsigned int*)raw;
    int okInt = 1, okFloat = 1;
    for (int i = t; i < (BATCH * SEQ) / 4; i += 256) {
        unsigned int v = w[i];
        if (v > 1u) okInt = 0;
        if (v != 0u && v != 0x3F800000u) okFloat = 0;
    }
    if (!okInt)   atomicAnd(&sInt, 0);
    if (!okFloat) atomicAnd(&sFloat, 0);
    __syncthreads();
    if (sInt) {
        const int* ip = (const int*)raw;
        for (int i = t; i < BATCH * SEQ; i += 256) g_mask[i] = (unsigned char)(ip[i] != 0);
    } else if (sFloat) {
        const float* fp = (const float*)raw;
        for (int i = t; i < BATCH * SEQ; i += 256) g_mask[i] = (unsigned char)(fp[i] != 0.0f);
    } else {
        const unsigned char* cp = (const unsigned char*)raw;
        for (int i = t; i < BATCH * SEQ; i += 256) g_mask[i] = (unsigned char)(cp[i] != 0);
    }
}

// ---------------- fp32 -> bf16 hi/lo split ----------------
__global__ void __launch_bounds__(256) split_kernel(
    const float* __restrict__ in, __nv_bfloat16* __restrict__ h,
    __nv_bfloat16* __restrict__ l, int n4)
{
    int i = blockIdx.x * 256 + threadIdx.x;
    if (i >= n4) return;
    float4 v = ((const float4*)in)[i];
    float a[4] = { v.x, v.y, v.z, v.w };
    __nv_bfloat16 hv[4], lv[4];
    #pragma unroll
    for (int q = 0; q < 4; q++) {
        hv[q] = __float2bfloat16(a[q]);
        lv[q] = __float2bfloat16(a[q] - __bfloat162float(hv[q]));
    }
    ((uint2*)h)[i] = *(uint2*)hv;
    ((uint2*)l)[i] = *(uint2*)lv;
}

// ---------------- HMMA split-bf16 GEMM (projections) ----------------
// D[m][n] = alpha * sum_k A[m][k] * B[n][k] (NT). 3-split Ah*Bh+Ah*Bl+Al*Bh.
// EPI: 0 = fp32 C0 ; 1 = bf16 hi/lo planes C0/C1 ; 2 = V-transpose hi/lo planes.
template<int BN, int EPI>
__global__ void __launch_bounds__(256, 1)
mm_hmma(const __nv_bfloat16* __restrict__ Ah, const __nv_bfloat16* __restrict__ Al,
        int lda,
        const __nv_bfloat16* __restrict__ Bh, const __nv_bfloat16* __restrict__ Bl,
        int ldb,
        void* __restrict__ C0, void* __restrict__ C1,
        int ldc, int K, float alpha)
{
    constexpr int BM  = 128;
    constexpr int MF  = 4;
    constexpr int NF  = BN / 32;
    constexpr int APL = BM * 80;
    constexpr int BPL = BN * 80;
    constexpr int STG = 2 * APL + 2 * BPL;

    extern __shared__ __align__(16) char smem[];
    const uint32_t sb = s2u(smem);
    const int t = threadIdx.x, wid = t >> 5, lid = t & 31;
    const int wm = wid >> 2, wn = wid & 3;
    const int warp_m0 = wm * 64;
    const int warp_n0 = wn * (NF * 8);
    const int m0 = blockIdx.y * BM, n0 = blockIdx.x * BN;

    float acc[MF][NF][4];
    #pragma unroll
    for (int i = 0; i < MF; i++)
        #pragma unroll
        for (int j = 0; j < NF; j++)
            #pragma unroll
            for (int q = 0; q < 4; q++) acc[i][j][q] = 0.0f;

    auto load_tile = [&](int st, int c) {
        const int k0 = c << 5;
        const uint32_t sA = sb + st * STG;
        const uint32_t sB = sA + 2 * APL;
        #pragma unroll
        for (int i = t; i < BM * 4; i += 256) {
            const int row = i >> 2, cc = i & 3;
            const size_t go = (size_t)(m0 + row) * lda + k0 + cc * 8;
            const uint32_t so = sA + row * 80 + cc * 16;
            cpa16(so, Ah + go);
            cpa16(so + APL, Al + go);
        }
        #pragma unroll
        for (int i = t; i < BN * 4; i += 256) {
            const int row = i >> 2, cc = i & 3;
            const size_t go = (size_t)(n0 + row) * ldb + k0 + cc * 8;
            const uint32_t so = sB + row * 80 + cc * 16;
            cpa16(so, Bh + go);
            cpa16(so + BPL, Bl + go);
        }
    };

    const int nt = K >> 5;
    load_tile(0, 0);
    CP_COMMIT();

    for (int c = 0; c < nt; ++c) {
        if (c + 1 < nt) {
            load_tile((c + 1) & 1, c + 1);
            CP_COMMIT();
            CP_WAIT1();
        } else {
            CP_WAIT0();
        }
        __syncthreads();

        const uint32_t sA = sb + (c & 1) * STG;
        const uint32_t sB = sA + 2 * APL;
        #pragma unroll
        for (int ks = 0; ks < 2; ++ks) {
            uint32_t ah[MF][4], al[MF][4];
            #pragma unroll
            for (int mf = 0; mf < MF; ++mf) {
                const int lrow = warp_m0 + mf * 16 + (lid & 15);
                const int lch  = ks * 2 + (lid >> 4);
                const uint32_t ad = sA + lrow * 80 + lch * 16;
                ldsm4(ad, ah[mf]);
                ldsm4(ad + APL, al[mf]);
            }
            uint32_t bh[NF][2], bl[NF][2];
            #pragma unroll
            for (int nf = 0; nf < NF; ++nf) {
                const int lrow = warp_n0 + nf * 8 + (lid & 7);
                const int lch  = ks * 2 + ((lid >> 3) & 1);
                const uint32_t bd = sB + lrow * 80 + lch * 16;
                ldsm2(bd, bh[nf]);
                ldsm2(bd + BPL, bl[nf]);
            }
            #pragma unroll
            for (int mf = 0; mf < MF; ++mf)
                #pragma unroll
                for (int nf = 0; nf < NF; ++nf) {
                    mma16816(acc[mf][nf], ah[mf], bh[nf]);
                    mma16816(acc[mf][nf], ah[mf], bl[nf]);
                    mma16816(acc[mf][nf], al[mf], bh[nf]);
                }
        }
        __syncthreads();
    }

    const int qrow = lid >> 2, qcol = (lid & 3) * 2;
    #pragma unroll
    for (int mf = 0; mf < MF; ++mf) {
        #pragma unroll
        for (int h = 0; h < 2; ++h) {
            const int m = m0 + warp_m0 + mf * 16 + qrow + h * 8;
            if constexpr (EPI == 0) {
                float* C = (float*)C0 + (size_t)m * ldc + n0 + warp_n0 + qcol;
                #pragma unroll
                for (int nf = 0; nf < NF; ++nf) {
                    float2 v;
                    v.x = alpha * acc[mf][nf][h * 2 + 0];
                    v.y = alpha * acc[mf][nf][h * 2 + 1];
                    *(float2*)(C + nf * 8) = v;
                }
            } else if constexpr (EPI == 1) {
                const size_t base = (size_t)m * ldc + n0 + warp_n0 + qcol;
                __nv_bfloat16* H = (__nv_bfloat16*)C0 + base;
                __nv_bfloat16* L = (__nv_bfloat16*)C1 + base;
                #pragma unroll
                for (int nf = 0; nf < NF; ++nf) {
                    uint32_t hp, lp;
                    split2(alpha * acc[mf][nf][h * 2 + 0],
                           alpha * acc[mf][nf][h * 2 + 1], hp, lp);
                    *(uint32_t*)(H + nf * 8) = hp;
                    *(uint32_t*)(L + nf * 8) = lp;
                }
            } else {  // EPI == 2 : V transpose -> out[b][e][s]
                const int bb = m >> 11, sq = m & (SEQ - 1);
                __nv_bfloat16* H = (__nv_bfloat16*)C0;
                __nv_bfloat16* L = (__nv_bfloat16*)C1;
                #pragma unroll
                for (int nf = 0; nf < NF; ++nf) {
                    #pragma unroll
                    for (int q = 0; q < 2; ++q) {
                        const float v = acc[mf][nf][h * 2 + q];
                        const __nv_bfloat16 hv = __float2bfloat16(v);
                        const __nv_bfloat16 lv = __float2bfloat16(v - __bfloat162float(hv));
                        const int e = n0 + warp_n0 + nf * 8 + qcol + q;
                        const size_t ad = (size_t)bb * ((size_t)EMB * SEQ)
                                        + (size_t)e * SEQ + sq;
                        H[ad] = hv; L[ad] = lv;
                    }
                }
            }
        }
    }
}

// ---------------- fused flash attention (QK^T + masked softmax + PV) ----------------
// grid (S/128, B*H); 8 warps; warp owns 16 q-rows. 3-split HMMA both GEMMs.
__global__ void __launch_bounds__(256, 1)
flash_kernel(const __nv_bfloat16* __restrict__ qh, const __nv_bfloat16* __restrict__ ql,
             const __nv_bfloat16* __restrict__ kh, const __nv_bfloat16* __restrict__ kl,
             const __nv_bfloat16* __restrict__ vth, const __nv_bfloat16* __restrict__ vtl,
             __nv_bfloat16* __restrict__ oh, __nv_bfloat16* __restrict__ ol)
{
    extern __shared__ __align__(16) char smem[];
    const uint32_t sb = s2u(smem);
    const int t = threadIdx.x, wid = t >> 5, lid = t & 31;
    const int z = blockIdx.y, b = z >> 4, h = z & 15;
    const int q0 = blockIdx.x * 128;

    constexpr int KP = 144, VP = 272;          // smem pitches (conflict-free ldmatrix)
    constexpr int QPL = 128 * KP;              // 18432 per Q plane
    constexpr int KPL = 128 * KP;
    constexpr int VPL = 64 * VP;               // 17408 per V plane
    constexpr int STG0  = 2 * QPL;             // 36864
    constexpr int SOFFV = 2 * KPL;             // V planes offset within stage
    constexpr int SOFFM = SOFFV + 2 * VPL;     // 71680 mask offset
    constexpr int STGSZ = SOFFM + 128;         // 71808

    const size_t SE = (size_t)SEQ * EMB;
    const __nv_bfloat16* Qh = qh  + (size_t)b * SE + (size_t)h * DK;
    const __nv_bfloat16* Ql = ql  + (size_t)b * SE + (size_t)h * DK;
    const __nv_bfloat16* Kh = kh  + (size_t)b * SE + (size_t)h * DK;
    const __nv_bfloat16* Kl = kl  + (size_t)b * SE + (size_t)h * DK;
    const __nv_bfloat16* Vh = vth + (size_t)b * ((size_t)EMB * SEQ) + (size_t)(h * DK) * SEQ;
    const __nv_bfloat16* Vl = vtl + (size_t)b * ((size_t)EMB * SEQ) + (size_t)(h * DK) * SEQ;

    // prologue: Q tile
    #pragma unroll
    for (int i = t; i < 1024; i += 256) {
        const int row = i >> 3, ch = i & 7;
        const size_t g = (size_t)(q0 + row) * EMB + ch * 8;
        const uint32_t so = sb + row * KP + ch * 16;
        cpa16(so, Qh + g); cpa16(so + QPL, Ql + g);
    }
    auto load_kv = [&](int stage, int c) {
        const int kb = c << 7;
        const uint32_t base = sb + STG0 + stage * STGSZ;
        #pragma unroll
        for (int i = t; i < 1024; i += 256) {
            const int row = i >> 3, ch = i & 7;
            const size_t g = (size_t)(kb + row) * EMB + ch * 8;
            const uint32_t so = base + row * KP + ch * 16;
            cpa16(so, Kh + g); cpa16(so + KPL, Kl + g);
        }
        #pragma unroll
        for (int i = t; i < 1024; i += 256) {
            const int row = i >> 4, ch = i & 15;
            const size_t g = (size_t)row * SEQ + kb + ch * 8;
            const uint32_t so = base + SOFFV + row * VP + ch * 16;
            cpa16(so, Vh + g); cpa16(so + VPL, Vl + g);
        }
        if (t < 8) cpa16(base + SOFFM + t * 16, g_mask + b * SEQ + kb + t * 16);
    };

    load_kv(0, 0);
    CP_COMMIT();
    CP_WAIT0();
    __syncthreads();

    // Q fragments held in registers for the whole kernel
    uint32_t qfh[4][4], qfl[4][4];
    #pragma unroll
    for (int ks = 0; ks < 4; ks++) {
        const uint32_t ad = sb + (wid * 16 + (lid & 15)) * KP + (ks * 2 + (lid >> 4)) * 16;
        ldsm4(ad, qfh[ks]);
        ldsm4(ad + QPL, qfl[ks]);
    }

    float o_[8][4];
    #pragma unroll
    for (int i = 0; i < 8; i++)
        #pragma unroll
        for (int j = 0; j < 4; j++) o_[i][j] = 0.0f;
    float m0 = -1e30f, m1 = -1e30f, l0 = 0.0f, l1 = 0.0f;
    const int tq = lid & 3;

    for (int c = 0; c < 16; ++c) {
        if (c + 1 < 16) { load_kv((c + 1) & 1, c + 1); CP_COMMIT(); CP_WAIT1(); }
        else            { CP_WAIT0(); }
        __syncthreads();
        const uint32_t stg = sb + STG0 + (c & 1) * STGSZ;

        // ---- S = Q K^T (3-split) ----
        float s_[16][4];
        #pragma unroll
        for (int i = 0; i < 16; i++)
            #pragma unroll
            for (int j = 0; j < 4; j++) s_[i][j] = 0.0f;
        #pragma unroll
        for (int ks = 0; ks < 4; ++ks) {
            #pragma unroll
            for (int nf = 0; nf < 16; ++nf) {
                const uint32_t ad = stg + (nf * 8 + (lid & 7)) * KP
                                  + (ks * 2 + ((lid >> 3) & 1)) * 16;
                uint32_t kf[2], kfl[2];
                ldsm2(ad, kf); ldsm2(ad + KPL, kfl);
                mma16816(s_[nf], qfh[ks], kf);
                mma16816(s_[nf], qfh[ks], kfl);
                mma16816(s_[nf], qfl[ks], kf);
            }
        }

        // ---- masked online softmax ----
        const unsigned char* mptr = (const unsigned char*)smem + STG0 + (c & 1) * STGSZ + SOFFM;
        float tmx0 = -1e30f, tmx1 = -1e30f;
        #pragma unroll
        for (int nf = 0; nf < 16; ++nf) {
            const uchar2 mk = *(const uchar2*)(mptr + nf * 8 + 2 * tq);
            const float v0 = mk.x ? -1e9f : 0.125f * s_[nf][0];
            const float v1 = mk.y ? -1e9f : 0.125f * s_[nf][1];
            const float v2 = mk.x ? -1e9f : 0.125f * s_[nf][2];
            const float v3 = mk.y ? -1e9f : 0.125f * s_[nf][3];
            s_[nf][0] = v0; s_[nf][1] = v1; s_[nf][2] = v2; s_[nf][3] = v3;
            tmx0 = fmaxf(tmx0, fmaxf(v0, v1));
            tmx1 = fmaxf(tmx1, fmaxf(v2, v3));
        }
        tmx0 = fmaxf(tmx0, __shfl_xor_sync(0xffffffffu, tmx0, 1));
        tmx0 = fmaxf(tmx0, __shfl_xor_sync(0xffffffffu, tmx0, 2));
        tmx1 = fmaxf(tmx1, __shfl_xor_sync(0xffffffffu, tmx1, 1));
        tmx1 = fmaxf(tmx1, __shfl_xor_sync(0xffffffffu, tmx1, 2));
        const float mn0 = fmaxf(m0, tmx0), mn1 = fmaxf(m1, tmx1);
        const float a0 = __expf(m0 - mn0), a1 = __expf(m1 - mn1);
        m0 = mn0; m1 = mn1;
        float sum0 = 0.0f, sum1 = 0.0f;
        #pragma unroll
        for (int nf = 0; nf < 16; ++nf) {
            const float p0 = __expf(s_[nf][0] - m0);
            const float p1 = __expf(s_[nf][1] - m0);
            const float p2 = __expf(s_[nf][2] - m1);
            const float p3 = __expf(s_[nf][3] - m1);
            s_[nf][0] = p0; s_[nf][1] = p1; s_[nf][2] = p2; s_[nf][3] = p3;
            sum0 += p0 + p1; sum1 += p2 + p3;
        }
        sum0 += __shfl_xor_sync(0xffffffffu, sum0, 1);
        sum0 += __shfl_xor_sync(0xffffffffu, sum0, 2);
        sum1 += __shfl_xor_sync(0xffffffffu, sum1, 1);
        sum1 += __shfl_xor_sync(0xffffffffu, sum1, 2);
        l0 = l0 * a0 + sum0;
        l1 = l1 * a1 + sum1;
        #pragma unroll
        for (int nf = 0; nf < 8; ++nf) {
            o_[nf][0] *= a0; o_[nf][1] *= a0;
            o_[nf][2] *= a1; o_[nf][3] *= a1;
        }

        // ---- O += P V (3-split; P fragments straight from S registers) ----
        #pragma unroll
        for (int ks = 0; ks < 8; ++ks) {
            uint32_t ph4[4], pl4[4];
            split2(s_[2 * ks][0],     s_[2 * ks][1],     ph4[0], pl4[0]);
            split2(s_[2 * ks][2],     s_[2 * ks][3],     ph4[1], pl4[1]);
            split2(s_[2 * ks + 1][0], s_[2 * ks + 1][1], ph4[2], pl4[2]);
            split2(s_[2 * ks + 1][2], s_[2 * ks + 1][3], ph4[3], pl4[3]);
            #pragma unroll
            for (int nf = 0; nf < 8; ++nf) {
                const uint32_t ad = stg + SOFFV + (nf * 8 + (lid & 7)) * VP
                                  + (ks * 2 + ((lid >> 3) & 1)) * 16;
                uint32_t vf[2], vfl[2];
                ldsm2(ad, vf); ldsm2(ad + VPL, vfl);
                mma16816(o_[nf], ph4, vf);
                mma16816(o_[nf], ph4, vfl);
                mma16816(o_[nf], pl4, vf);
            }
        }
        __syncthreads();
    }

    // ---- epilogue: O /= l, write split bf16 planes ----
    const float inv0 = 1.0f / l0, inv1 = 1.0f / l1;
    const int g = lid >> 2;
    const size_t r0 = (size_t)(b * SEQ + q0 + wid * 16 + g) * EMB + h * DK + 2 * tq;
    const size_t r1 = r0 + (size_t)8 * EMB;
    #pragma unroll
    for (int nf = 0; nf < 8; ++nf) {
        uint32_t hi0, lo0, hi1, lo1;
        split2(o_[nf][0] * inv0, o_[nf][1] * inv0, hi0, lo0);
        split2(o_[nf][2] * inv1, o_[nf][3] * inv1, hi1, lo1);
        *(uint32_t*)(oh + r0 + nf * 8) = hi0;
        *(uint32_t*)(ol + r0 + nf * 8) = lo0;
        *(uint32_t*)(oh + r1 + nf * 8) = hi1;
        *(uint32_t*)(ol + r1 + nf * 8) = lo1;
    }
}

// ---------------- launch ----------------
extern "C" void kernel_launch(void* const* d_in, const int* in_sizes, int n_in,
                              void* d_out, int out_size)
{
    const float* x  = (const float*)d_in[0];
    const void*  mk = d_in[1];
    const float* wq = (const float*)d_in[2];
    const float* wk = (const float*)d_in[3];
    const float* wv = (const float*)d_in[4];
    const float* wo = (const float*)d_in[5];
    float* out = (float*)d_out;

    __nv_bfloat16 *xh, *xl, *wh, *wl, *qh, *ql, *kh, *kl, *vth, *vtl, *ath, *atl;
    cudaGetSymbolAddress((void**)&xh,  g_x_hi);
    cudaGetSymbolAddress((void**)&xl,  g_x_lo);
    cudaGetSymbolAddress((void**)&wh,  g_w_hi);
    cudaGetSymbolAddress((void**)&wl,  g_w_lo);
    cudaGetSymbolAddress((void**)&qh,  g_q_hi);
    cudaGetSymbolAddress((void**)&ql,  g_q_lo);
    cudaGetSymbolAddress((void**)&kh,  g_k_hi);
    cudaGetSymbolAddress((void**)&kl,  g_k_lo);
    cudaGetSymbolAddress((void**)&vth, g_vt_hi);
    cudaGetSymbolAddress((void**)&vtl, g_vt_lo);
    cudaGetSymbolAddress((void**)&ath, g_at_hi);
    cudaGetSymbolAddress((void**)&atl, g_at_lo);

    const int SM128 = 2 * (2 * 128 * 80 + 2 * 128 * 80);     // 81920
    const int SMFLASH = 2 * 128 * 144 + 2 * 71808;           // 180480
    cudaFuncSetAttribute(mm_hmma<128, 0>, cudaFuncAttributeMaxDynamicSharedMemorySize, SM128);
    cudaFuncSetAttribute(mm_hmma<128, 1>, cudaFuncAttributeMaxDynamicSharedMemorySize, SM128);
    cudaFuncSetAttribute(mm_hmma<128, 2>, cudaFuncAttributeMaxDynamicSharedMemorySize, SM128);
    cudaFuncSetAttribute(flash_kernel, cudaFuncAttributeMaxDynamicSharedMemorySize, SMFLASH);

    // 0) canonicalize mask
    mask_canon_kernel<<<1, 256>>>(mk);

    // 1) fp32 -> bf16 hi/lo splits
    const int NX4 = (MTOK * EMB) / 4, NW4 = (EMB * EMB) / 4;
    const size_t WSZ = (size_t)EMB * EMB;
    split_kernel<<<(NX4 + 255) / 256, 256>>>(x,  xh, xl, NX4);
    split_kernel<<<(NW4 + 255) / 256, 256>>>(wq, wh + 0 * WSZ, wl + 0 * WSZ, NW4);
    split_kernel<<<(NW4 + 255) / 256, 256>>>(wk, wh + 1 * WSZ, wl + 1 * WSZ, NW4);
    split_kernel<<<(NW4 + 255) / 256, 256>>>(wv, wh + 2 * WSZ, wl + 2 * WSZ, NW4);
    split_kernel<<<(NW4 + 255) / 256, 256>>>(wo, wh + 3 * WSZ, wl + 3 * WSZ, NW4);

    const dim3 gproj(EMB / 128, MTOK / 128, 1);

    // 2) projections: Q,K -> split planes ; V -> transposed split planes
    mm_hmma<128, 1><<<gproj, 256, SM128>>>(
        xh, xl, EMB, wh + 0 * WSZ, wl + 0 * WSZ, EMB, qh, ql, EMB, EMB, 1.0f);
    mm_hmma<128, 1><<<gproj, 256, SM128>>>(
        xh, xl, EMB, wh + 1 * WSZ, wl + 1 * WSZ, EMB, kh, kl, EMB, EMB, 1.0f);
    mm_hmma<128, 2><<<gproj, 256, SM128>>>(
        xh, xl, EMB, wh + 2 * WSZ, wl + 2 * WSZ, EMB, vth, vtl, EMB, EMB, 1.0f);

    // 3) fused attention -> att split planes
    const dim3 gflash(SEQ / 128, ZBH);
    flash_kernel<<<gflash, 256, SMFLASH>>>(qh, ql, kh, kl, vth, vtl, ath, atl);

    // 4) out = att @ wo^T (fp32 epilogue)
    mm_hmma<128, 0><<<gproj, 256, SM128>>>(
        ath, atl, EMB, wh + 3 * WSZ, wl + 3 * WSZ, EMB, out, nullptr, EMB, EMB, 1.0f);
}

// round 10
// speedup vs baseline: 3.1406x; 1.0773x over previous
#include <cuda_runtime.h>
#include <cuda_bf16.h>
#include <cstdint>

// ---------------- problem constants ----------------
#define BATCH 2
#define SEQ   2048
#define EMB   1024
#define HEADS 16
#define DK    64
#define MTOK  (BATCH * SEQ)            // 4096
#define ZBH   (BATCH * HEADS)          // 32
#define PLANE ((size_t)MTOK * EMB)     // elements per hi/lo plane

// ---------------- device scratch ----------------
__device__ __align__(16) __nv_bfloat16 g_x_hi [PLANE];
__device__ __align__(16) __nv_bfloat16 g_x_lo [PLANE];
__device__ __align__(16) __nv_bfloat16 g_w_hi [4][(size_t)EMB * EMB];   // wq,wk,wv,wo contiguous
__device__ __align__(16) __nv_bfloat16 g_w_lo [4][(size_t)EMB * EMB];
__device__ __align__(16) __nv_bfloat16 g_q    [2 * PLANE];              // hi | lo
__device__ __align__(16) __nv_bfloat16 g_k    [2 * PLANE];              // hi | lo
__device__ __align__(16) __nv_bfloat16 g_vt_hi[(size_t)BATCH * EMB * SEQ];  // [b][e][s]
__device__ __align__(16) __nv_bfloat16 g_vt_lo[(size_t)BATCH * EMB * SEQ];
__device__ __align__(16) __nv_bfloat16 g_at_hi[PLANE];
__device__ __align__(16) __nv_bfloat16 g_at_lo[PLANE];
__device__ __align__(16) unsigned char g_mask[BATCH * SEQ];

// ---------------- base-ISA PTX helpers ----------------
__device__ __forceinline__ uint32_t s2u(const void* p) {
    uint32_t a;
    asm("{ .reg .u64 t; cvta.to.shared.u64 t, %1; cvt.u32.u64 %0, t; }" : "=r"(a) : "l"(p));
    return a;
}
__device__ __forceinline__ void cpa16(uint32_t s, const void* g) {
    asm volatile("cp.async.cg.shared.global [%0], [%1], 16;" :: "r"(s), "l"(g));
}
#define CP_COMMIT() asm volatile("cp.async.commit_group;" ::: "memory")
#define CP_WAIT1()  asm volatile("cp.async.wait_group 1;"  ::: "memory")
#define CP_WAIT0()  asm volatile("cp.async.wait_group 0;"  ::: "memory")

__device__ __forceinline__ void ldsm4(uint32_t a, uint32_t r[4]) {
    asm volatile("ldmatrix.sync.aligned.m8n8.x4.shared.b16 {%0,%1,%2,%3}, [%4];"
        : "=r"(r[0]), "=r"(r[1]), "=r"(r[2]), "=r"(r[3]) : "r"(a));
}
__device__ __forceinline__ void mma16816(float c[4], const uint32_t a[4], uint32_t b0, uint32_t b1) {
    asm volatile(
        "mma.sync.aligned.m16n8k16.row.col.f32.bf16.bf16.f32 "
        "{%0,%1,%2,%3}, {%4,%5,%6,%7}, {%8,%9}, {%0,%1,%2,%3};"
        : "+f"(c[0]), "+f"(c[1]), "+f"(c[2]), "+f"(c[3])
        : "r"(a[0]), "r"(a[1]), "r"(a[2]), "r"(a[3]), "r"(b0), "r"(b1));
}
__device__ __forceinline__ void split2(float a, float b, uint32_t& hi, uint32_t& lo) {
    __nv_bfloat16 ha = __float2bfloat16(a), hb = __float2bfloat16(b);
    __nv_bfloat16 la = __float2bfloat16(a - __bfloat162float(ha));
    __nv_bfloat16 lb = __float2bfloat16(b - __bfloat162float(hb));
    __nv_bfloat162 hv; hv.x = ha; hv.y = hb;
    __nv_bfloat162 lv; lv.x = la; lv.y = lb;
    hi = *(uint32_t*)&hv; lo = *(uint32_t*)&lv;
}

// ---------------- mask canonicalization ----------------
__global__ void mask_canon_kernel(const void* __restrict__ raw) {
    __shared__ int sInt, sFloat;
    int t = threadIdx.x;
    if (t == 0) { sInt = 1; sFloat = 1; }
    __syncthreads();
    const unsigned int* w = (const unsigned int*)raw;
    int okInt = 1, okFloat = 1;
    for (int i = t; i < (BATCH * SEQ) / 4; i += 256) {
        unsigned int v = w[i];
        if (v > 1u) okInt = 0;
        if (v != 0u && v != 0x3F800000u) okFloat = 0;
    }
    if (!okInt)   atomicAnd(&sInt, 0);
    if (!okFloat) atomicAnd(&sFloat, 0);
    __syncthreads();
    if (sInt) {
        const int* ip = (const int*)raw;
        for (int i = t; i < BATCH * SEQ; i += 256) g_mask[i] = (unsigned char)(ip[i] != 0);
    } else if (sFloat) {
        const float* fp = (const float*)raw;
        for (int i = t; i < BATCH * SEQ; i += 256) g_mask[i] = (unsigned char)(fp[i] != 0.0f);
    } else {
        const unsigned char* cp = (const unsigned char*)raw;
        for (int i = t; i < BATCH * SEQ; i += 256) g_mask[i] = (unsigned char)(cp[i] != 0);
    }
}

// ---------------- fp32 -> bf16 hi/lo split ----------------
__global__ void __launch_bounds__(256) split_kernel(
    const float* __restrict__ in, __nv_bfloat16* __restrict__ h,
    __nv_bfloat16* __restrict__ l, int n4)
{
    int i = blockIdx.x * 256 + threadIdx.x;
    if (i >= n4) return;
    float4 v = ((const float4*)in)[i];
    float a[4] = { v.x, v.y, v.z, v.w };
    __nv_bfloat16 hv[4], lv[4];
    #pragma unroll
    for (int q = 0; q < 4; q++) {
        hv[q] = __float2bfloat16(a[q]);
        lv[q] = __float2bfloat16(a[q] - __bfloat162float(hv[q]));
    }
    ((uint2*)h)[i] = *(uint2*)hv;
    ((uint2*)l)[i] = *(uint2*)lv;
}

// ---------------- big-tile HMMA split-bf16 GEMM ----------------
// 256x128 CTA tile, 8 warps (4M x 2N), warp tile 64x64, BK=32, double buffer.
// D = A B^T (NT), 3-split Ah*Bh + Ah*Bl + Al*Bh, fp32 accum.
// EPIMODE 0: fp32 out. EPIMODE 3: QKV dispatch (bx<8 Q, <16 K, else V-transpose).
template<int EPIMODE>
__global__ void __launch_bounds__(256, 1)
mm_big(const __nv_bfloat16* __restrict__ Ah, const __nv_bfloat16* __restrict__ Al,
       const __nv_bfloat16* __restrict__ Bh, const __nv_bfloat16* __restrict__ Bl,
       float* __restrict__ Cf)
{
    constexpr int BM = 256, BN = 128;
    constexpr int APL = BM * 80;
    constexpr int BPL = BN * 80;
    constexpr int STG = 2 * APL + 2 * BPL;

    extern __shared__ __align__(16) char smem[];
    const uint32_t sb = s2u(smem);
    const int t = threadIdx.x, wid = t >> 5, lid = t & 31;
    const int warp_m0 = (wid >> 1) * 64;
    const int warp_n0 = (wid & 1) * 64;
    const int m0 = blockIdx.y * BM, n0 = blockIdx.x * BN;

    float acc[4][8][4];
    #pragma unroll
    for (int i = 0; i < 4; i++)
        #pragma unroll
        for (int j = 0; j < 8; j++)
            #pragma unroll
            for (int q = 0; q < 4; q++) acc[i][j][q] = 0.0f;

    auto load_tile = [&](int st, int c) {
        const int k0 = c << 5;
        const uint32_t sA = sb + st * STG;
        const uint32_t sB = sA + 2 * APL;
        #pragma unroll
        for (int i = t; i < BM * 4; i += 256) {
            const int row = i >> 2, cc = i & 3;
            const size_t go = (size_t)(m0 + row) * EMB + k0 + cc * 8;
            const uint32_t so = sA + row * 80 + cc * 16;
            cpa16(so, Ah + go);
            cpa16(so + APL, Al + go);
        }
        #pragma unroll
        for (int i = t; i < BN * 4; i += 256) {
            const int row = i >> 2, cc = i & 3;
            const size_t go = (size_t)(n0 + row) * EMB + k0 + cc * 8;
            const uint32_t so = sB + row * 80 + cc * 16;
            cpa16(so, Bh + go);
            cpa16(so + BPL, Bl + go);
        }
    };

    const int nt = EMB >> 5;
    load_tile(0, 0);
    CP_COMMIT();

    for (int c = 0; c < nt; ++c) {
        if (c + 1 < nt) { load_tile((c + 1) & 1, c + 1); CP_COMMIT(); CP_WAIT1(); }
        else            { CP_WAIT0(); }
        __syncthreads();

        const uint32_t sA = sb + (c & 1) * STG;
        const uint32_t sB = sA + 2 * APL;
        #pragma unroll
        for (int ks = 0; ks < 2; ++ks) {
            uint32_t ah[4][4], al[4][4];
            #pragma unroll
            for (int mf = 0; mf < 4; ++mf) {
                const uint32_t ad = sA + (warp_m0 + mf * 16 + (lid & 15)) * 80
                                  + (ks * 2 + (lid >> 4)) * 16;
                ldsm4(ad, ah[mf]);
                ldsm4(ad + APL, al[mf]);
            }
            #pragma unroll
            for (int j = 0; j < 4; ++j) {
                const uint32_t bd = sB + (warp_n0 + j * 16 + ((lid >> 4) << 3) + (lid & 7)) * 80
                                  + (ks * 2 + ((lid >> 3) & 1)) * 16;
                uint32_t bh4[4], bl4[4];
                ldsm4(bd, bh4);
                ldsm4(bd + BPL, bl4);
                #pragma unroll
                for (int mf = 0; mf < 4; ++mf) {
                    mma16816(acc[mf][2 * j],     ah[mf], bh4[0], bh4[1]);
                    mma16816(acc[mf][2 * j],     ah[mf], bl4[0], bl4[1]);
                    mma16816(acc[mf][2 * j],     al[mf], bh4[0], bh4[1]);
                    mma16816(acc[mf][2 * j + 1], ah[mf], bh4[2], bh4[3]);
                    mma16816(acc[mf][2 * j + 1], ah[mf], bl4[2], bl4[3]);
                    mma16816(acc[mf][2 * j + 1], al[mf], bh4[2], bh4[3]);
                }
            }
        }
        __syncthreads();
    }

    // ---- epilogue ----
    const int qrow = lid >> 2, qcol = (lid & 3) * 2;
    if constexpr (EPIMODE == 0) {
        #pragma unroll
        for (int mf = 0; mf < 4; ++mf)
            #pragma unroll
            for (int h = 0; h < 2; ++h) {
                const int m = m0 + warp_m0 + mf * 16 + qrow + h * 8;
                float* C = Cf + (size_t)m * EMB + n0 + warp_n0 + qcol;
                #pragma unroll
                for (int nf = 0; nf < 8; ++nf) {
                    float2 v;
                    v.x = acc[mf][nf][h * 2 + 0];
                    v.y = acc[mf][nf][h * 2 + 1];
                    *(float2*)(C + nf * 8) = v;
                }
            }
    } else {
        const int bx = blockIdx.x;
        if (bx < 16) {                       // Q or K split planes (hi | lo contiguous)
            __nv_bfloat16* H = (bx < 8) ? g_q : g_k;
            __nv_bfloat16* L = H + PLANE;
            const int col0 = (n0 & 1023) + warp_n0 + qcol;
            #pragma unroll
            for (int mf = 0; mf < 4; ++mf)
                #pragma unroll
                for (int h = 0; h < 2; ++h) {
                    const int m = m0 + warp_m0 + mf * 16 + qrow + h * 8;
                    const size_t base = (size_t)m * EMB + col0;
                    #pragma unroll
                    for (int nf = 0; nf < 8; ++nf) {
                        uint32_t hp, lp;
                        split2(acc[mf][nf][h * 2 + 0], acc[mf][nf][h * 2 + 1], hp, lp);
                        *(uint32_t*)(H + base + nf * 8) = hp;
                        *(uint32_t*)(L + base + nf * 8) = lp;
                    }
                }
        } else {                             // V transpose -> [b][e][s] planes
            #pragma unroll
            for (int mf = 0; mf < 4; ++mf)
                #pragma unroll
                for (int h = 0; h < 2; ++h) {
                    const int m = m0 + warp_m0 + mf * 16 + qrow + h * 8;
                    const int bb = m >> 11, sq = m & (SEQ - 1);
                    #pragma unroll
                    for (int nf = 0; nf < 8; ++nf)
                        #pragma unroll
                        for (int q = 0; q < 2; ++q) {
                            const float v = acc[mf][nf][h * 2 + q];
                            const __nv_bfloat16 hv = __float2bfloat16(v);
                            const __nv_bfloat16 lv = __float2bfloat16(v - __bfloat162float(hv));
                            const int e = (n0 - 2048) + warp_n0 + nf * 8 + qcol + q;
                            const size_t ad = (size_t)bb * ((size_t)EMB * SEQ)
                                            + (size_t)e * SEQ + sq;
                            g_vt_hi[ad] = hv; g_vt_lo[ad] = lv;
                        }
                }
        }
    }
}

// ---------------- fused flash attention ----------------
__global__ void __launch_bounds__(256, 1)
flash_kernel(const __nv_bfloat16* __restrict__ qp, const __nv_bfloat16* __restrict__ kp,
             const __nv_bfloat16* __restrict__ vth, const __nv_bfloat16* __restrict__ vtl,
             __nv_bfloat16* __restrict__ oh, __nv_bfloat16* __restrict__ ol)
{
    extern __shared__ __align__(16) char smem[];
    const uint32_t sb = s2u(smem);
    const int t = threadIdx.x, wid = t >> 5, lid = t & 31;
    const int z = blockIdx.y, b = z >> 4, h = z & 15;
    const int q0 = blockIdx.x * 128;

    constexpr int KP = 144, VP = 272;
    constexpr int QPL = 128 * KP;
    constexpr int KPL = 128 * KP;
    constexpr int VPL = 64 * VP;
    constexpr int STG0  = 2 * QPL;
    constexpr int SOFFV = 2 * KPL;
    constexpr int SOFFM = SOFFV + 2 * VPL;
    constexpr int STGSZ = SOFFM + 128;

    const size_t SE = (size_t)SEQ * EMB;
    const __nv_bfloat16* Qh = qp + (size_t)b * SE + (size_t)h * DK;
    const __nv_bfloat16* Ql = Qh + PLANE;
    const __nv_bfloat16* Kh = kp + (size_t)b * SE + (size_t)h * DK;
    const __nv_bfloat16* Kl = Kh + PLANE;
    const __nv_bfloat16* Vh = vth + (size_t)b * ((size_t)EMB * SEQ) + (size_t)(h * DK) * SEQ;
    const __nv_bfloat16* Vl = vtl + (size_t)b * ((size_t)EMB * SEQ) + (size_t)(h * DK) * SEQ;

    #pragma unroll
    for (int i = t; i < 1024; i += 256) {
        const int row = i >> 3, ch = i & 7;
        const size_t g = (size_t)(q0 + row) * EMB + ch * 8;
        const uint32_t so = sb + row * KP + ch * 16;
        cpa16(so, Qh + g); cpa16(so + QPL, Ql + g);
    }
    auto load_kv = [&](int stage, int c) {
        const int kb = c << 7;
        const uint32_t base = sb + STG0 + stage * STGSZ;
        #pragma unroll
        for (int i = t; i < 1024; i += 256) {
            const int row = i >> 3, ch = i & 7;
            const size_t g = (size_t)(kb + row) * EMB + ch * 8;
            const uint32_t so = base + row * KP + ch * 16;
            cpa16(so, Kh + g); cpa16(so + KPL, Kl + g);
        }
        #pragma unroll
        for (int i = t; i < 1024; i += 256) {
            const int row = i >> 4, ch = i & 15;
            const size_t g = (size_t)row * SEQ + kb + ch * 8;
            const uint32_t so = base + SOFFV + row * VP + ch * 16;
            cpa16(so, Vh + g); cpa16(so + VPL, Vl + g);
        }
        if (t < 8) cpa16(base + SOFFM + t * 16, g_mask + b * SEQ + kb + t * 16);
    };

    load_kv(0, 0);
    CP_COMMIT();
    CP_WAIT0();
    __syncthreads();

    uint32_t qfh[4][4], qfl[4][4];
    #pragma unroll
    for (int ks = 0; ks < 4; ks++) {
        const uint32_t ad = sb + (wid * 16 + (lid & 15)) * KP + (ks * 2 + (lid >> 4)) * 16;
        ldsm4(ad, qfh[ks]);
        ldsm4(ad + QPL, qfl[ks]);
    }

    float o_[8][4];
    #pragma unroll
    for (int i = 0; i < 8; i++)
        #pragma unroll
        for (int j = 0; j < 4; j++) o_[i][j] = 0.0f;
    float m0 = -1e30f, m1 = -1e30f, l0 = 0.0f, l1 = 0.0f;
    const int tq = lid & 3;

    for (int c = 0; c < 16; ++c) {
        if (c + 1 < 16) { load_kv((c + 1) & 1, c + 1); CP_COMMIT(); CP_WAIT1(); }
        else            { CP_WAIT0(); }
        __syncthreads();
        const uint32_t stg = sb + STG0 + (c & 1) * STGSZ;

        float s_[16][4];
        #pragma unroll
        for (int i = 0; i < 16; i++)
            #pragma unroll
            for (int j = 0; j < 4; j++) s_[i][j] = 0.0f;
        #pragma unroll
        for (int ks = 0; ks < 4; ++ks) {
            #pragma unroll
            for (int j = 0; j < 8; ++j) {
                const uint32_t ad = stg + (j * 16 + ((lid >> 4) << 3) + (lid & 7)) * KP
                                  + (ks * 2 + ((lid >> 3) & 1)) * 16;
                uint32_t kf[4], kfl[4];
                ldsm4(ad, kf); ldsm4(ad + KPL, kfl);
                mma16816(s_[2 * j],     qfh[ks], kf[0],  kf[1]);
                mma16816(s_[2 * j],     qfh[ks], kfl[0], kfl[1]);
                mma16816(s_[2 * j],     qfl[ks], kf[0],  kf[1]);
                mma16816(s_[2 * j + 1], qfh[ks], kf[2],  kf[3]);
                mma16816(s_[2 * j + 1], qfh[ks], kfl[2], kfl[3]);
                mma16816(s_[2 * j + 1], qfl[ks], kf[2],  kf[3]);
            }
        }

        const unsigned char* mptr = (const unsigned char*)smem + STG0 + (c & 1) * STGSZ + SOFFM;
        float tmx0 = -1e30f, tmx1 = -1e30f;
        #pragma unroll
        for (int nf = 0; nf < 16; ++nf) {
            const uchar2 mk = *(const uchar2*)(mptr + nf * 8 + 2 * tq);
            const float v0 = mk.x ? -1e9f : 0.125f * s_[nf][0];
            const float v1 = mk.y ? -1e9f : 0.125f * s_[nf][1];
            const float v2 = mk.x ? -1e9f : 0.125f * s_[nf][2];
            const float v3 = mk.y ? -1e9f : 0.125f * s_[nf][3];
            s_[nf][0] = v0; s_[nf][1] = v1; s_[nf][2] = v2; s_[nf][3] = v3;
            tmx0 = fmaxf(tmx0, fmaxf(v0, v1));
            tmx1 = fmaxf(tmx1, fmaxf(v2, v3));
        }
        tmx0 = fmaxf(tmx0, __shfl_xor_sync(0xffffffffu, tmx0, 1));
        tmx0 = fmaxf(tmx0, __shfl_xor_sync(0xffffffffu, tmx0, 2));
        tmx1 = fmaxf(tmx1, __shfl_xor_sync(0xffffffffu, tmx1, 1));
        tmx1 = fmaxf(tmx1, __shfl_xor_sync(0xffffffffu, tmx1, 2));
        const float mn0 = fmaxf(m0, tmx0), mn1 = fmaxf(m1, tmx1);
        const float a0 = __expf(m0 - mn0), a1 = __expf(m1 - mn1);
        m0 = mn0; m1 = mn1;
        float sum0 = 0.0f, sum1 = 0.0f;
        #pragma unroll
        for (int nf = 0; nf < 16; ++nf) {
            const float p0 = __expf(s_[nf][0] - m0);
            const float p1 = __expf(s_[nf][1] - m0);
            const float p2 = __expf(s_[nf][2] - m1);
            const float p3 = __expf(s_[nf][3] - m1);
            s_[nf][0] = p0; s_[nf][1] = p1; s_[nf][2] = p2; s_[nf][3] = p3;
            sum0 += p0 + p1; sum1 += p2 + p3;
        }
        sum0 += __shfl_xor_sync(0xffffffffu, sum0, 1);
        sum0 += __shfl_xor_sync(0xffffffffu, sum0, 2);
        sum1 += __shfl_xor_sync(0xffffffffu, sum1, 1);
        sum1 += __shfl_xor_sync(0xffffffffu, sum1, 2);
        l0 = l0 * a0 + sum0;
        l1 = l1 * a1 + sum1;
        #pragma unroll
        for (int nf = 0; nf < 8; ++nf) {
            o_[nf][0] *= a0; o_[nf][1] *= a0;
            o_[nf][2] *= a1; o_[nf][3] *= a1;
        }

        #pragma unroll
        for (int ks = 0; ks < 8; ++ks) {
            uint32_t ph4[4], pl4[4];
            split2(s_[2 * ks][0],     s_[2 * ks][1],     ph4[0], pl4[0]);
            split2(s_[2 * ks][2],     s_[2 * ks][3],     ph4[1], pl4[1]);
            split2(s_[2 * ks + 1][0], s_[2 * ks + 1][1], ph4[2], pl4[2]);
            split2(s_[2 * ks + 1][2], s_[2 * ks + 1][3], ph4[3], pl4[3]);
            #pragma unroll
            for (int j = 0; j < 4; ++j) {
                const uint32_t ad = stg + SOFFV + (j * 16 + ((lid >> 4) << 3) + (lid & 7)) * VP
                                  + (ks * 2 + ((lid >> 3) & 1)) * 16;
                uint32_t vf[4], vfl[4];
                ldsm4(ad, vf); ldsm4(ad + VPL, vfl);
                mma16816(o_[2 * j],     ph4, vf[0],  vf[1]);
                mma16816(o_[2 * j],     ph4, vfl[0], vfl[1]);
                mma16816(o_[2 * j],     pl4, vf[0],  vf[1]);
                mma16816(o_[2 * j + 1], ph4, vf[2],  vf[3]);
                mma16816(o_[2 * j + 1], ph4, vfl[2], vfl[3]);
                mma16816(o_[2 * j + 1], pl4, vf[2],  vf[3]);
            }
        }
        __syncthreads();
    }

    const float inv0 = 1.0f / l0, inv1 = 1.0f / l1;
    const int g = lid >> 2;
    const size_t r0 = (size_t)(b * SEQ + q0 + wid * 16 + g) * EMB + h * DK + 2 * tq;
    const size_t r1 = r0 + (size_t)8 * EMB;
    #pragma unroll
    for (int nf = 0; nf < 8; ++nf) {
        uint32_t hi0, lo0, hi1, lo1;
        split2(o_[nf][0] * inv0, o_[nf][1] * inv0, hi0, lo0);
        split2(o_[nf][2] * inv1, o_[nf][3] * inv1, hi1, lo1);
        *(uint32_t*)(oh + r0 + nf * 8) = hi0;
        *(uint32_t*)(ol + r0 + nf * 8) = lo0;
        *(uint32_t*)(oh + r1 + nf * 8) = hi1;
        *(uint32_t*)(ol + r1 + nf * 8) = lo1;
    }
}

// ---------------- launch ----------------
extern "C" void kernel_launch(void* const* d_in, const int* in_sizes, int n_in,
                              void* d_out, int out_size)
{
    const float* x  = (const float*)d_in[0];
    const void*  mk = d_in[1];
    const float* wq = (const float*)d_in[2];
    const float* wk = (const float*)d_in[3];
    const float* wv = (const float*)d_in[4];
    const float* wo = (const float*)d_in[5];
    float* out = (float*)d_out;

    __nv_bfloat16 *xh, *xl, *wh, *wl, *qp, *kp, *vth, *vtl, *ath, *atl;
    cudaGetSymbolAddress((void**)&xh,  g_x_hi);
    cudaGetSymbolAddress((void**)&xl,  g_x_lo);
    cudaGetSymbolAddress((void**)&wh,  g_w_hi);
    cudaGetSymbolAddress((void**)&wl,  g_w_lo);
    cudaGetSymbolAddress((void**)&qp,  g_q);
    cudaGetSymbolAddress((void**)&kp,  g_k);
    cudaGetSymbolAddress((void**)&vth, g_vt_hi);
    cudaGetSymbolAddress((void**)&vtl, g_vt_lo);
    cudaGetSymbolAddress((void**)&ath, g_at_hi);
    cudaGetSymbolAddress((void**)&atl, g_at_lo);

    const int SMBIG = 2 * (2 * 256 * 80 + 2 * 128 * 80);     // 122880
    const int SMFLASH = 2 * 128 * 144 + 2 * 71808;           // 180480
    cudaFuncSetAttribute(mm_big<0>, cudaFuncAttributeMaxDynamicSharedMemorySize, SMBIG);
    cudaFuncSetAttribute(mm_big<3>, cudaFuncAttributeMaxDynamicSharedMemorySize, SMBIG);
    cudaFuncSetAttribute(flash_kernel, cudaFuncAttributeMaxDynamicSharedMemorySize, SMFLASH);

    mask_canon_kernel<<<1, 256>>>(mk);

    const int NX4 = (MTOK * EMB) / 4, NW4 = (EMB * EMB) / 4;
    const size_t WSZ = (size_t)EMB * EMB;
    split_kernel<<<(NX4 + 255) / 256, 256>>>(x,  xh, xl, NX4);
    split_kernel<<<(NW4 + 255) / 256, 256>>>(wq, wh + 0 * WSZ, wl + 0 * WSZ, NW4);
    split_kernel<<<(NW4 + 255) / 256, 256>>>(wk, wh + 1 * WSZ, wl + 1 * WSZ, NW4);
    split_kernel<<<(NW4 + 255) / 256, 256>>>(wv, wh + 2 * WSZ, wl + 2 * WSZ, NW4);
    split_kernel<<<(NW4 + 255) / 256, 256>>>(wo, wh + 3 * WSZ, wl + 3 * WSZ, NW4);

    // merged QKV projection: one launch, 24x16 CTAs (epilogue dispatch on bx)
    const dim3 gqkv(24, 16);
    mm_big<3><<<gqkv, 256, SMBIG>>>(xh, xl, wh, wl, nullptr);

    // fused attention -> att planes
    const dim3 gflash(SEQ / 128, ZBH);
    flash_kernel<<<gflash, 256, SMFLASH>>>(qp, kp, vth, vtl, ath, atl);

    // final projection (fp32 out)
    const dim3 gfin(8, 16);
    mm_big<0><<<gfin, 256, SMBIG>>>(ath, atl, wh + 3 * WSZ, wl + 3 * WSZ, out);
}

// round 11
// speedup vs baseline: 3.1679x; 1.0087x over previous
#include <cuda_runtime.h>
#include <cuda_bf16.h>
#include <cstdint>

// ---------------- problem constants ----------------
#define BATCH 2
#define SEQ   2048
#define EMB   1024
#define HEADS 16
#define DK    64
#define MTOK  (BATCH * SEQ)            // 4096
#define ZBH   (BATCH * HEADS)          // 32
#define PLANE ((size_t)MTOK * EMB)     // elements per hi/lo plane

// ---------------- device scratch ----------------
__device__ __align__(16) __nv_bfloat16 g_x_hi [PLANE];
__device__ __align__(16) __nv_bfloat16 g_x_lo [PLANE];
__device__ __align__(16) __nv_bfloat16 g_w_hi [4][(size_t)EMB * EMB];   // wq,wk,wv,wo contiguous
__device__ __align__(16) __nv_bfloat16 g_w_lo [4][(size_t)EMB * EMB];
__device__ __align__(16) __nv_bfloat16 g_q    [2 * PLANE];              // hi | lo
__device__ __align__(16) __nv_bfloat16 g_k    [2 * PLANE];              // hi | lo
__device__ __align__(16) __nv_bfloat16 g_v    [2 * PLANE];              // hi | lo, row-major [tok][emb]
__device__ __align__(16) __nv_bfloat16 g_at_hi[PLANE];
__device__ __align__(16) __nv_bfloat16 g_at_lo[PLANE];
__device__ __align__(16) unsigned char g_mask[BATCH * SEQ];

// ---------------- base-ISA PTX helpers ----------------
__device__ __forceinline__ uint32_t s2u(const void* p) {
    uint32_t a;
    asm("{ .reg .u64 t; cvta.to.shared.u64 t, %1; cvt.u32.u64 %0, t; }" : "=r"(a) : "l"(p));
    return a;
}
__device__ __forceinline__ void cpa16(uint32_t s, const void* g) {
    asm volatile("cp.async.cg.shared.global [%0], [%1], 16;" :: "r"(s), "l"(g));
}
#define CP_COMMIT() asm volatile("cp.async.commit_group;" ::: "memory")
#define CP_WAIT1()  asm volatile("cp.async.wait_group 1;"  ::: "memory")
#define CP_WAIT0()  asm volatile("cp.async.wait_group 0;"  ::: "memory")

__device__ __forceinline__ void ldsm4(uint32_t a, uint32_t r[4]) {
    asm volatile("ldmatrix.sync.aligned.m8n8.x4.shared.b16 {%0,%1,%2,%3}, [%4];"
        : "=r"(r[0]), "=r"(r[1]), "=r"(r[2]), "=r"(r[3]) : "r"(a));
}
__device__ __forceinline__ void ldsm4t(uint32_t a, uint32_t r[4]) {
    asm volatile("ldmatrix.sync.aligned.m8n8.x4.trans.shared.b16 {%0,%1,%2,%3}, [%4];"
        : "=r"(r[0]), "=r"(r[1]), "=r"(r[2]), "=r"(r[3]) : "r"(a));
}
__device__ __forceinline__ void mma16816(float c[4], const uint32_t a[4], uint32_t b0, uint32_t b1) {
    asm volatile(
        "mma.sync.aligned.m16n8k16.row.col.f32.bf16.bf16.f32 "
        "{%0,%1,%2,%3}, {%4,%5,%6,%7}, {%8,%9}, {%0,%1,%2,%3};"
        : "+f"(c[0]), "+f"(c[1]), "+f"(c[2]), "+f"(c[3])
        : "r"(a[0]), "r"(a[1]), "r"(a[2]), "r"(a[3]), "r"(b0), "r"(b1));
}
__device__ __forceinline__ void split2(float a, float b, uint32_t& hi, uint32_t& lo) {
    __nv_bfloat16 ha = __float2bfloat16(a), hb = __float2bfloat16(b);
    __nv_bfloat16 la = __float2bfloat16(a - __bfloat162float(ha));
    __nv_bfloat16 lb = __float2bfloat16(b - __bfloat162float(hb));
    __nv_bfloat162 hv; hv.x = ha; hv.y = hb;
    __nv_bfloat162 lv; lv.x = la; lv.y = lb;
    hi = *(uint32_t*)&hv; lo = *(uint32_t*)&lv;
}

// ---------------- mask canonicalization ----------------
__global__ void mask_canon_kernel(const void* __restrict__ raw) {
    __shared__ int sInt, sFloat;
    int t = threadIdx.x;
    if (t == 0) { sInt = 1; sFloat = 1; }
    __syncthreads();
    const unsigned int* w = (const unsigned int*)raw;
    int okInt = 1, okFloat = 1;
    for (int i = t; i < (BATCH * SEQ) / 4; i += 256) {
        unsigned int v = w[i];
        if (v > 1u) okInt = 0;
        if (v != 0u && v != 0x3F800000u) okFloat = 0;
    }
    if (!okInt)   atomicAnd(&sInt, 0);
    if (!okFloat) atomicAnd(&sFloat, 0);
    __syncthreads();
    if (sInt) {
        const int* ip = (const int*)raw;
        for (int i = t; i < BATCH * SEQ; i += 256) g_mask[i] = (unsigned char)(ip[i] != 0);
    } else if (sFloat) {
        const float* fp = (const float*)raw;
        for (int i = t; i < BATCH * SEQ; i += 256) g_mask[i] = (unsigned char)(fp[i] != 0.0f);
    } else {
        const unsigned char* cp = (const unsigned char*)raw;
        for (int i = t; i < BATCH * SEQ; i += 256) g_mask[i] = (unsigned char)(cp[i] != 0);
    }
}

// ---------------- fp32 -> bf16 hi/lo split ----------------
__global__ void __launch_bounds__(256) split_kernel(
    const float* __restrict__ in, __nv_bfloat16* __restrict__ h,
    __nv_bfloat16* __restrict__ l, int n4)
{
    int i = blockIdx.x * 256 + threadIdx.x;
    if (i >= n4) return;
    float4 v = ((const float4*)in)[i];
    float a[4] = { v.x, v.y, v.z, v.w };
    __nv_bfloat16 hv[4], lv[4];
    #pragma unroll
    for (int q = 0; q < 4; q++) {
        hv[q] = __float2bfloat16(a[q]);
        lv[q] = __float2bfloat16(a[q] - __bfloat162float(hv[q]));
    }
    ((uint2*)h)[i] = *(uint2*)hv;
    ((uint2*)l)[i] = *(uint2*)lv;
}

// ---------------- big-tile HMMA split-bf16 GEMM ----------------
// 256x128 CTA tile, 8 warps (4M x 2N), warp tile 64x64, BK=32, double buffer.
// D = A B^T (NT), 3-split Ah*Bh + Ah*Bl + Al*Bh, fp32 accum.
// EPIMODE 0: fp32 out to Cf. EPIMODE 3: QKV -> split planes (bx<8 Q, <16 K, else V).
template<int EPIMODE>
__global__ void __launch_bounds__(256, 1)
mm_big(const __nv_bfloat16* __restrict__ Ah, const __nv_bfloat16* __restrict__ Al,
       const __nv_bfloat16* __restrict__ Bh, const __nv_bfloat16* __restrict__ Bl,
       float* __restrict__ Cf)
{
    constexpr int BM = 256, BN = 128;
    constexpr int APL = BM * 80;
    constexpr int BPL = BN * 80;
    constexpr int STG = 2 * APL + 2 * BPL;

    extern __shared__ __align__(16) char smem[];
    const uint32_t sb = s2u(smem);
    const int t = threadIdx.x, wid = t >> 5, lid = t & 31;
    const int warp_m0 = (wid >> 1) * 64;
    const int warp_n0 = (wid & 1) * 64;
    const int m0 = blockIdx.y * BM, n0 = blockIdx.x * BN;

    float acc[4][8][4];
    #pragma unroll
    for (int i = 0; i < 4; i++)
        #pragma unroll
        for (int j = 0; j < 8; j++)
            #pragma unroll
            for (int q = 0; q < 4; q++) acc[i][j][q] = 0.0f;

    auto load_tile = [&](int st, int c) {
        const int k0 = c << 5;
        const uint32_t sA = sb + st * STG;
        const uint32_t sB = sA + 2 * APL;
        #pragma unroll
        for (int i = t; i < BM * 4; i += 256) {
            const int row = i >> 2, cc = i & 3;
            const size_t go = (size_t)(m0 + row) * EMB + k0 + cc * 8;
            const uint32_t so = sA + row * 80 + cc * 16;
            cpa16(so, Ah + go);
            cpa16(so + APL, Al + go);
        }
        #pragma unroll
        for (int i = t; i < BN * 4; i += 256) {
            const int row = i >> 2, cc = i & 3;
            const size_t go = (size_t)(n0 + row) * EMB + k0 + cc * 8;
            const uint32_t so = sB + row * 80 + cc * 16;
            cpa16(so, Bh + go);
            cpa16(so + BPL, Bl + go);
        }
    };

    const int nt = EMB >> 5;
    load_tile(0, 0);
    CP_COMMIT();

    for (int c = 0; c < nt; ++c) {
        if (c + 1 < nt) { load_tile((c + 1) & 1, c + 1); CP_COMMIT(); CP_WAIT1(); }
        else            { CP_WAIT0(); }
        __syncthreads();

        const uint32_t sA = sb + (c & 1) * STG;
        const uint32_t sB = sA + 2 * APL;
        #pragma unroll
        for (int ks = 0; ks < 2; ++ks) {
            uint32_t ah[4][4], al[4][4];
            #pragma unroll
            for (int mf = 0; mf < 4; ++mf) {
                const uint32_t ad = sA + (warp_m0 + mf * 16 + (lid & 15)) * 80
                                  + (ks * 2 + (lid >> 4)) * 16;
                ldsm4(ad, ah[mf]);
                ldsm4(ad + APL, al[mf]);
            }
            #pragma unroll
            for (int j = 0; j < 4; ++j) {
                const uint32_t bd = sB + (warp_n0 + j * 16 + ((lid >> 4) << 3) + (lid & 7)) * 80
                                  + (ks * 2 + ((lid >> 3) & 1)) * 16;
                uint32_t bh4[4], bl4[4];
                ldsm4(bd, bh4);
                ldsm4(bd + BPL, bl4);
                #pragma unroll
                for (int mf = 0; mf < 4; ++mf) {
                    mma16816(acc[mf][2 * j],     ah[mf], bh4[0], bh4[1]);
                    mma16816(acc[mf][2 * j],     ah[mf], bl4[0], bl4[1]);
                    mma16816(acc[mf][2 * j],     al[mf], bh4[0], bh4[1]);
                    mma16816(acc[mf][2 * j + 1], ah[mf], bh4[2], bh4[3]);
                    mma16816(acc[mf][2 * j + 1], ah[mf], bl4[2], bl4[3]);
                    mma16816(acc[mf][2 * j + 1], al[mf], bh4[2], bh4[3]);
                }
            }
        }
        __syncthreads();
    }

    // ---- epilogue ----
    const int qrow = lid >> 2, qcol = (lid & 3) * 2;
    if constexpr (EPIMODE == 0) {
        #pragma unroll
        for (int mf = 0; mf < 4; ++mf)
            #pragma unroll
            for (int h = 0; h < 2; ++h) {
                const int m = m0 + warp_m0 + mf * 16 + qrow + h * 8;
                float* C = Cf + (size_t)m * EMB + n0 + warp_n0 + qcol;
                #pragma unroll
                for (int nf = 0; nf < 8; ++nf) {
                    float2 v;
                    v.x = acc[mf][nf][h * 2 + 0];
                    v.y = acc[mf][nf][h * 2 + 1];
                    *(float2*)(C + nf * 8) = v;
                }
            }
    } else {
        const int bx = blockIdx.x;
        __nv_bfloat16* H = (bx < 8) ? g_q : (bx < 16 ? g_k : g_v);
        __nv_bfloat16* L = H + PLANE;
        const int col0 = (n0 & 1023) + warp_n0 + qcol;
        #pragma unroll
        for (int mf = 0; mf < 4; ++mf)
            #pragma unroll
            for (int h = 0; h < 2; ++h) {
                const int m = m0 + warp_m0 + mf * 16 + qrow + h * 8;
                const size_t base = (size_t)m * EMB + col0;
                #pragma unroll
                for (int nf = 0; nf < 8; ++nf) {
                    uint32_t hp, lp;
                    split2(acc[mf][nf][h * 2 + 0], acc[mf][nf][h * 2 + 1], hp, lp);
                    *(uint32_t*)(H + base + nf * 8) = hp;
                    *(uint32_t*)(L + base + nf * 8) = lp;
                }
            }
    }
}

// ---------------- fused flash attention ----------------
// grid (S/128, B*H); 8 warps; warp owns 16 q-rows. K and V both stored
// row-major [tok][emb]; V fragments via ldmatrix.trans.
__global__ void __launch_bounds__(256, 1)
flash_kernel(const __nv_bfloat16* __restrict__ qp, const __nv_bfloat16* __restrict__ kp,
             const __nv_bfloat16* __restrict__ vp,
             __nv_bfloat16* __restrict__ oh, __nv_bfloat16* __restrict__ ol)
{
    extern __shared__ __align__(16) char smem[];
    const uint32_t sb = s2u(smem);
    const int t = threadIdx.x, wid = t >> 5, lid = t & 31;
    const int z = blockIdx.y, b = z >> 4, h = z & 15;
    const int q0 = blockIdx.x * 128;

    constexpr int KP = 144;                // pitch for Q/K/V tiles (128B row + 16B pad)
    constexpr int QPL = 128 * KP;          // 18432 per plane
    constexpr int KPL = 128 * KP;
    constexpr int VPL = 128 * KP;
    constexpr int STG0  = 2 * QPL;         // 36864 (Q hi/lo)
    constexpr int SOFFV = 2 * KPL;         // 36864 within stage
    constexpr int SOFFM = SOFFV + 2 * VPL; // 73728
    constexpr int STGSZ = SOFFM + 128;     // 73856

    const size_t SE = (size_t)SEQ * EMB;
    const __nv_bfloat16* Qh = qp + (size_t)b * SE + (size_t)h * DK;
    const __nv_bfloat16* Ql = Qh + PLANE;
    const __nv_bfloat16* Kh = kp + (size_t)b * SE + (size_t)h * DK;
    const __nv_bfloat16* Kl = Kh + PLANE;
    const __nv_bfloat16* Vh = vp + (size_t)b * SE + (size_t)h * DK;
    const __nv_bfloat16* Vl = Vh + PLANE;

    #pragma unroll
    for (int i = t; i < 1024; i += 256) {
        const int row = i >> 3, ch = i & 7;
        const size_t g = (size_t)(q0 + row) * EMB + ch * 8;
        const uint32_t so = sb + row * KP + ch * 16;
        cpa16(so, Qh + g); cpa16(so + QPL, Ql + g);
    }
    auto load_kv = [&](int stage, int c) {
        const int kb = c << 7;
        const uint32_t base = sb + STG0 + stage * STGSZ;
        #pragma unroll
        for (int i = t; i < 1024; i += 256) {
            const int row = i >> 3, ch = i & 7;
            const size_t g = (size_t)(kb + row) * EMB + ch * 8;
            const uint32_t so = base + row * KP + ch * 16;
            cpa16(so, Kh + g);         cpa16(so + KPL, Kl + g);
            cpa16(so + SOFFV, Vh + g); cpa16(so + SOFFV + VPL, Vl + g);
        }
        if (t < 8) cpa16(base + SOFFM + t * 16, g_mask + b * SEQ + kb + t * 16);
    };

    load_kv(0, 0);
    CP_COMMIT();
    CP_WAIT0();
    __syncthreads();

    uint32_t qfh[4][4], qfl[4][4];
    #pragma unroll
    for (int ks = 0; ks < 4; ks++) {
        const uint32_t ad = sb + (wid * 16 + (lid & 15)) * KP + (ks * 2 + (lid >> 4)) * 16;
        ldsm4(ad, qfh[ks]);
        ldsm4(ad + QPL, qfl[ks]);
    }

    float o_[8][4];
    #pragma unroll
    for (int i = 0; i < 8; i++)
        #pragma unroll
        for (int j = 0; j < 4; j++) o_[i][j] = 0.0f;
    float m0 = -1e30f, m1 = -1e30f, l0 = 0.0f, l1 = 0.0f;
    const int tq = lid & 3;

    for (int c = 0; c < 16; ++c) {
        if (c + 1 < 16) { load_kv((c + 1) & 1, c + 1); CP_COMMIT(); CP_WAIT1(); }
        else            { CP_WAIT0(); }
        __syncthreads();
        const uint32_t stg = sb + STG0 + (c & 1) * STGSZ;

        // ---- S = Q K^T (3-split) ----
        float s_[16][4];
        #pragma unroll
        for (int i = 0; i < 16; i++)
            #pragma unroll
            for (int j = 0; j < 4; j++) s_[i][j] = 0.0f;
        #pragma unroll
        for (int ks = 0; ks < 4; ++ks) {
            #pragma unroll
            for (int j = 0; j < 8; ++j) {
                const uint32_t ad = stg + (j * 16 + ((lid >> 4) << 3) + (lid & 7)) * KP
                                  + (ks * 2 + ((lid >> 3) & 1)) * 16;
                uint32_t kf[4], kfl[4];
                ldsm4(ad, kf); ldsm4(ad + KPL, kfl);
                mma16816(s_[2 * j],     qfh[ks], kf[0],  kf[1]);
                mma16816(s_[2 * j],     qfh[ks], kfl[0], kfl[1]);
                mma16816(s_[2 * j],     qfl[ks], kf[0],  kf[1]);
                mma16816(s_[2 * j + 1], qfh[ks], kf[2],  kf[3]);
                mma16816(s_[2 * j + 1], qfh[ks], kfl[2], kfl[3]);
                mma16816(s_[2 * j + 1], qfl[ks], kf[2],  kf[3]);
            }
        }

        // ---- masked online softmax ----
        const unsigned char* mptr = (const unsigned char*)smem + STG0 + (c & 1) * STGSZ + SOFFM;
        float tmx0 = -1e30f, tmx1 = -1e30f;
        #pragma unroll
        for (int nf = 0; nf < 16; ++nf) {
            const uchar2 mk = *(const uchar2*)(mptr + nf * 8 + 2 * tq);
            const float v0 = mk.x ? -1e9f : 0.125f * s_[nf][0];
            const float v1 = mk.y ? -1e9f : 0.125f * s_[nf][1];
            const float v2 = mk.x ? -1e9f : 0.125f * s_[nf][2];
            const float v3 = mk.y ? -1e9f : 0.125f * s_[nf][3];
            s_[nf][0] = v0; s_[nf][1] = v1; s_[nf][2] = v2; s_[nf][3] = v3;
            tmx0 = fmaxf(tmx0, fmaxf(v0, v1));
            tmx1 = fmaxf(tmx1, fmaxf(v2, v3));
        }
        tmx0 = fmaxf(tmx0, __shfl_xor_sync(0xffffffffu, tmx0, 1));
        tmx0 = fmaxf(tmx0, __shfl_xor_sync(0xffffffffu, tmx0, 2));
        tmx1 = fmaxf(tmx1, __shfl_xor_sync(0xffffffffu, tmx1, 1));
        tmx1 = fmaxf(tmx1, __shfl_xor_sync(0xffffffffu, tmx1, 2));
        const float mn0 = fmaxf(m0, tmx0), mn1 = fmaxf(m1, tmx1);
        const float a0 = __expf(m0 - mn0), a1 = __expf(m1 - mn1);
        m0 = mn0; m1 = mn1;
        float sum0 = 0.0f, sum1 = 0.0f;
        #pragma unroll
        for (int nf = 0; nf < 16; ++nf) {
            const float p0 = __expf(s_[nf][0] - m0);
            const float p1 = __expf(s_[nf][1] - m0);
            const float p2 = __expf(s_[nf][2] - m1);
            const float p3 = __expf(s_[nf][3] - m1);
            s_[nf][0] = p0; s_[nf][1] = p1; s_[nf][2] = p2; s_[nf][3] = p3;
            sum0 += p0 + p1; sum1 += p2 + p3;
        }
        sum0 += __shfl_xor_sync(0xffffffffu, sum0, 1);
        sum0 += __shfl_xor_sync(0xffffffffu, sum0, 2);
        sum1 += __shfl_xor_sync(0xffffffffu, sum1, 1);
        sum1 += __shfl_xor_sync(0xffffffffu, sum1, 2);
        l0 = l0 * a0 + sum0;
        l1 = l1 * a1 + sum1;
        #pragma unroll
        for (int nf = 0; nf < 8; ++nf) {
            o_[nf][0] *= a0; o_[nf][1] *= a0;
            o_[nf][2] *= a1; o_[nf][3] *= a1;
        }

        // ---- O += P V (3-split; V via ldmatrix.trans on [s][e] tile) ----
        #pragma unroll
        for (int ks = 0; ks < 8; ++ks) {
            uint32_t ph4[4], pl4[4];
            split2(s_[2 * ks][0],     s_[2 * ks][1],     ph4[0], pl4[0]);
            split2(s_[2 * ks][2],     s_[2 * ks][3],     ph4[1], pl4[1]);
            split2(s_[2 * ks + 1][0], s_[2 * ks + 1][1], ph4[2], pl4[2]);
            split2(s_[2 * ks + 1][2], s_[2 * ks + 1][3], ph4[3], pl4[3]);
            #pragma unroll
            for (int j = 0; j < 4; ++j) {
                // trans x4: lane groups -> (k-half, n-half) of the 16x16 tile
                const uint32_t ad = stg + SOFFV
                                  + (ks * 16 + (((lid >> 3) & 1) << 3) + (lid & 7)) * KP
                                  + (j * 16 + ((lid >> 4) << 3)) * 2;
                uint32_t vf[4], vfl[4];
                ldsm4t(ad, vf); ldsm4t(ad + VPL, vfl);
                mma16816(o_[2 * j],     ph4, vf[0],  vf[1]);
                mma16816(o_[2 * j],     ph4, vfl[0], vfl[1]);
                mma16816(o_[2 * j],     pl4, vf[0],  vf[1]);
                mma16816(o_[2 * j + 1], ph4, vf[2],  vf[3]);
                mma16816(o_[2 * j + 1], ph4, vfl[2], vfl[3]);
                mma16816(o_[2 * j + 1], pl4, vf[2],  vf[3]);
            }
        }
        __syncthreads();
    }

    // ---- epilogue: O /= l, write split bf16 planes ----
    const float inv0 = 1.0f / l0, inv1 = 1.0f / l1;
    const int g = lid >> 2;
    const size_t r0 = (size_t)(b * SEQ + q0 + wid * 16 + g) * EMB + h * DK + 2 * tq;
    const size_t r1 = r0 + (size_t)8 * EMB;
    #pragma unroll
    for (int nf = 0; nf < 8; ++nf) {
        uint32_t hi0, lo0, hi1, lo1;
        split2(o_[nf][0] * inv0, o_[nf][1] * inv0, hi0, lo0);
        split2(o_[nf][2] * inv1, o_[nf][3] * inv1, hi1, lo1);
        *(uint32_t*)(oh + r0 + nf * 8) = hi0;
        *(uint32_t*)(ol + r0 + nf * 8) = lo0;
        *(uint32_t*)(oh + r1 + nf * 8) = hi1;
        *(uint32_t*)(ol + r1 + nf * 8) = lo1;
    }
}

// ---------------- launch ----------------
extern "C" void kernel_launch(void* const* d_in, const int* in_sizes, int n_in,
                              void* d_out, int out_size)
{
    const float* x  = (const float*)d_in[0];
    const void*  mk = d_in[1];
    const float* wq = (const float*)d_in[2];
    const float* wk = (const float*)d_in[3];
    const float* wv = (const float*)d_in[4];
    const float* wo = (const float*)d_in[5];
    float* out = (float*)d_out;

    __nv_bfloat16 *xh, *xl, *wh, *wl, *qp, *kp, *vpp, *ath, *atl;
    cudaGetSymbolAddress((void**)&xh,  g_x_hi);
    cudaGetSymbolAddress((void**)&xl,  g_x_lo);
    cudaGetSymbolAddress((void**)&wh,  g_w_hi);
    cudaGetSymbolAddress((void**)&wl,  g_w_lo);
    cudaGetSymbolAddress((void**)&qp,  g_q);
    cudaGetSymbolAddress((void**)&kp,  g_k);
    cudaGetSymbolAddress((void**)&vpp, g_v);
    cudaGetSymbolAddress((void**)&ath, g_at_hi);
    cudaGetSymbolAddress((void**)&atl, g_at_lo);

    const int SMBIG = 2 * (2 * 256 * 80 + 2 * 128 * 80);     // 122880
    const int SMFLASH = 2 * 128 * 144 + 2 * 73856;           // 184576
    cudaFuncSetAttribute(mm_big<0>, cudaFuncAttributeMaxDynamicSharedMemorySize, SMBIG);
    cudaFuncSetAttribute(mm_big<3>, cudaFuncAttributeMaxDynamicSharedMemorySize, SMBIG);
    cudaFuncSetAttribute(flash_kernel, cudaFuncAttributeMaxDynamicSharedMemorySize, SMFLASH);

    mask_canon_kernel<<<1, 256>>>(mk);

    const int NX4 = (MTOK * EMB) / 4, NW4 = (EMB * EMB) / 4;
    const size_t WSZ = (size_t)EMB * EMB;
    split_kernel<<<(NX4 + 255) / 256, 256>>>(x,  xh, xl, NX4);
    split_kernel<<<(NW4 + 255) / 256, 256>>>(wq, wh + 0 * WSZ, wl + 0 * WSZ, NW4);
    split_kernel<<<(NW4 + 255) / 256, 256>>>(wk, wh + 1 * WSZ, wl + 1 * WSZ, NW4);
    split_kernel<<<(NW4 + 255) / 256, 256>>>(wv, wh + 2 * WSZ, wl + 2 * WSZ, NW4);
    split_kernel<<<(NW4 + 255) / 256, 256>>>(wo, wh + 3 * WSZ, wl + 3 * WSZ, NW4);

    // merged QKV projection: one launch, 24x16 CTAs (epilogue dispatch on bx)
    const dim3 gqkv(24, 16);
    mm_big<3><<<gqkv, 256, SMBIG>>>(xh, xl, wh, wl, nullptr);

    // fused attention -> att planes
    const dim3 gflash(SEQ / 128, ZBH);
    flash_kernel<<<gflash, 256, SMFLASH>>>(qp, kp, vpp, ath, atl);

    // final projection (fp32 out)
    const dim3 gfin(8, 16);
    mm_big<0><<<gfin, 256, SMBIG>>>(ath, atl, wh + 3 * WSZ, wl + 3 * WSZ, out);
}